// round 1
// baseline (speedup 1.0000x reference)
#include <cuda_runtime.h>
#include <math.h>

#define BSZ 4
#define DIM 64
#define HWN 65536          // 256*256
#define AS_STRIDE 36
#define BS_STRIDE 260
#define SS_STRIDE 33

// ---------------- device scratch (static, allocation-free) ----------------
__device__ float g_qkv [BSZ * 192 * HWN];   // [b][o=3*64][p]   (~201 MB)
__device__ float g_conv[BSZ * DIM * HWN];   // conv_feat        (~67 MB)
__device__ float g_outh[BSZ * DIM * HWN];   // horizontal attn out
__device__ float g_outv[BSZ * DIM * HWN];   // vertical attn out
__device__ float g_gx  [BSZ * DIM];
__device__ float g_cw  [BSZ];
__device__ float g_aw  [BSZ];
__device__ float g_norm[2 * BSZ * DIM];     // [0..255]=||q||, [256..511]=||k||

// ---------------- 1) per-channel spatial mean ----------------
__global__ void k_mean(const float* __restrict__ x) {
    int bc = blockIdx.x;
    int tid = threadIdx.x;
    const float* p = x + (size_t)bc * HWN;
    float s = 0.f;
    for (int i = tid; i < HWN; i += 256) s += p[i];
    __shared__ float red[256];
    red[tid] = s; __syncthreads();
    for (int o = 128; o; o >>= 1) { if (tid < o) red[tid] += red[tid + o]; __syncthreads(); }
    if (tid == 0) g_gx[bc] = red[0] * (1.0f / HWN);
}

// ---------------- 2) gate MLP (tiny) ----------------
__global__ void k_gate(const float* __restrict__ g1w, const float* __restrict__ g1b,
                       const float* __restrict__ g2w, const float* __restrict__ g2b) {
    int b = threadIdx.x;
    if (b >= BSZ) return;
    float h1[16];
    for (int j = 0; j < 16; j++) {
        float a = g1b[j];
        for (int c = 0; c < 64; c++) a += g_gx[b * 64 + c] * g1w[j * 64 + c];
        h1[j] = fmaxf(a, 0.f);
    }
    float l0 = g2b[0], l1 = g2b[1];
    for (int j = 0; j < 16; j++) { l0 += h1[j] * g2w[j]; l1 += h1[j] * g2w[16 + j]; }
    float m = fmaxf(l0, l1);
    float e0 = expf(l0 - m), e1 = expf(l1 - m);
    float inv = 1.f / (e0 + e1);
    g_cw[b] = e0 * inv;
    g_aw[b] = e1 * inv;
}

// ---------------- 3) fused depthwise 3x3 + 5x5 conv ----------------
__global__ void k_conv(const float* __restrict__ x,
                       const float* __restrict__ w3, const float* __restrict__ b3,
                       const float* __restrict__ w5, const float* __restrict__ b5) {
    long long idx = (long long)blockIdx.x * 256 + threadIdx.x;
    int bc = (int)(idx >> 16);
    int p  = (int)(idx & 65535);
    int c  = bc & 63;
    int h  = p >> 8, w = p & 255;
    __shared__ float s3[9], s5[25], sb[1];
    if (threadIdx.x < 9)  s3[threadIdx.x] = w3[c * 9 + threadIdx.x];
    if (threadIdx.x < 25) s5[threadIdx.x] = w5[c * 25 + threadIdx.x];
    if (threadIdx.x == 0) sb[0] = b3[c] + b5[c];
    __syncthreads();
    const float* xp = x + (size_t)bc * HWN;
    float acc = sb[0];
    #pragma unroll
    for (int dh = -2; dh <= 2; dh++) {
        int hh = h + dh;
        if ((unsigned)hh >= 256u) continue;
        const float* row = xp + hh * 256;
        #pragma unroll
        for (int dw = -2; dw <= 2; dw++) {
            int ww = w + dw;
            if ((unsigned)ww >= 256u) continue;
            float v = row[ww];
            acc += v * s5[(dh + 2) * 5 + (dw + 2)];
            if (dh >= -1 && dh <= 1 && dw >= -1 && dw <= 1)
                acc += v * s3[(dh + 1) * 3 + (dw + 1)];
        }
    }
    g_conv[idx] = acc;
}

// ---------------- 4) per-pixel QKV projection (192x64) ----------------
__global__ void k_qkv(const float* __restrict__ x, const float* __restrict__ wqkv) {
    __shared__ float ws[192 * 64];   // 48 KB
    for (int i = threadIdx.x; i < 192 * 64; i += 256) ws[i] = wqkv[i];
    __syncthreads();
    long long g = (long long)blockIdx.x * 256 + threadIdx.x;
    int b = (int)(g >> 16);
    int p = (int)(g & 65535);
    float xr[64];
    const float* xp = x + (size_t)b * 64 * HWN + p;
    #pragma unroll
    for (int c = 0; c < 64; c++) xr[c] = xp[(size_t)c * HWN];
    float* outp = g_qkv + (size_t)b * 192 * HWN + p;
    for (int o = 0; o < 192; o++) {
        const float4* wr = (const float4*)(ws + o * 64);
        float acc = 0.f;
        #pragma unroll
        for (int c4 = 0; c4 < 16; c4++) {
            float4 w4 = wr[c4];
            acc += w4.x * xr[c4 * 4] + w4.y * xr[c4 * 4 + 1]
                 + w4.z * xr[c4 * 4 + 2] + w4.w * xr[c4 * 4 + 3];
        }
        outp[(size_t)o * HWN] = acc;
    }
}

// ---------------- 5) slice L2 norms for q,k ----------------
__global__ void k_norm() {
    int s2 = blockIdx.x;                 // 0..511
    int which = s2 >> 8;                 // 0=q, 1=k
    int s = s2 & 255;
    int b = s >> 6, ch = s & 63;
    const float* p = g_qkv + ((size_t)b * 192 + which * 64 + ch) * HWN;
    float acc = 0.f;
    for (int i = threadIdx.x; i < HWN; i += 256) { float v = p[i]; acc += v * v; }
    __shared__ float red[256];
    red[threadIdx.x] = acc; __syncthreads();
    for (int o = 128; o; o >>= 1) { if (threadIdx.x < o) red[threadIdx.x] += red[threadIdx.x + o]; __syncthreads(); }
    if (threadIdx.x == 0) g_norm[s2] = fmaxf(sqrtf(red[0]), 1e-12f);
}

// ---------------- 6) dual-axis attention ----------------
// block = (slice s, direction dir, 32-wide tile t).  256 threads.
// S-tile (32 x 256) and O-tile accumulated in registers (32/thread),
// softmax over full contraction (256) in smem.
__global__ void __launch_bounds__(256, 2) k_attn(const float* __restrict__ scale) {
    extern __shared__ float sm[];
    float* As   = sm;                          // 32 * 36
    float* Bs   = As + 32 * AS_STRIDE;         // 32 * 260
    float* Ss   = Bs + 32 * BS_STRIDE;         // 256 * 33
    float* red  = Ss + 256 * SS_STRIDE;        // 8 * 33
    float* invs = red + 8 * 33;                // 32

    int bid = blockIdx.x;
    int s   = bid & 255;
    int t   = (bid >> 8) & 7;
    int dir = bid >> 11;
    int b = s >> 6, ch = s & 63, hd = ch & 7;
    float alpha = scale[hd] / (g_norm[s] * g_norm[256 + s]);
    const float* Q = g_qkv + ((size_t)b * 192 + ch) * HWN;
    const float* K = Q + (size_t)64 * HWN;
    const float* V = Q + (size_t)128 * HWN;
    int tid = threadIdx.x;
    int fb = tid >> 6;     // 0..3  -> 8-wide fragment (tile index)
    int fa = tid & 63;     // 0..63 -> 4-wide fragment (z / y)
    int t32 = t * 32;

    float acc[32];
    #pragma unroll
    for (int i = 0; i < 32; i++) acc[i] = 0.f;

    // ======== S phase: S[u][z] over contraction chunks of 32 ========
    for (int cc = 0; cc < 8; cc++) {
        int c0 = cc * 32;
        if (dir == 0) {
            // horizontal: S[xi][z] = sum_y Q[t32+xi][y] * K[z][y]
            for (int idx = tid; idx < 1024; idx += 256) {
                int xi = idx >> 5, yy = idx & 31;
                As[yy * AS_STRIDE + xi] = Q[(t32 + xi) * 256 + c0 + yy];
            }
            for (int idx = tid; idx < 8192; idx += 256) {
                int z = idx >> 5, yy = idx & 31;
                Bs[yy * BS_STRIDE + z] = K[z * 256 + c0 + yy];
            }
        } else {
            // vertical: S[yi][z] = sum_x Q[x][t32+yi] * K[x][z]
            for (int idx = tid; idx < 1024; idx += 256) {
                int xx = idx >> 5, yi = idx & 31;
                As[xx * AS_STRIDE + yi] = Q[(c0 + xx) * 256 + t32 + yi];
            }
            const float4* K4 = (const float4*)(K + c0 * 256);
            for (int idx = tid; idx < 2048; idx += 256) {
                int xx = idx >> 6, z4 = idx & 63;
                ((float4*)(Bs + xx * BS_STRIDE))[z4] = K4[xx * 64 + z4];
            }
        }
        __syncthreads();
        #pragma unroll 4
        for (int r = 0; r < 32; r++) {
            float4 a0 = *(const float4*)(As + r * AS_STRIDE + fb * 8);
            float4 a1 = *(const float4*)(As + r * AS_STRIDE + fb * 8 + 4);
            float4 bv = *(const float4*)(Bs + r * BS_STRIDE + fa * 4);
            float av[8] = {a0.x, a0.y, a0.z, a0.w, a1.x, a1.y, a1.z, a1.w};
            #pragma unroll
            for (int i = 0; i < 8; i++) {
                acc[i * 4 + 0] += av[i] * bv.x;
                acc[i * 4 + 1] += av[i] * bv.y;
                acc[i * 4 + 2] += av[i] * bv.z;
                acc[i * 4 + 3] += av[i] * bv.w;
            }
        }
        __syncthreads();
    }
    // store scaled S into smem: Ss[z][u]
    #pragma unroll
    for (int i = 0; i < 8; i++)
        #pragma unroll
        for (int j = 0; j < 4; j++)
            Ss[(fa * 4 + j) * SS_STRIDE + fb * 8 + i] = alpha * acc[i * 4 + j];
    __syncthreads();

    // ======== softmax over z per column u ========
    int u = tid & 31, rr = tid >> 5;
    float lm = -1e30f;
    for (int z = rr * 32; z < rr * 32 + 32; z++) lm = fmaxf(lm, Ss[z * SS_STRIDE + u]);
    red[rr * 33 + u] = lm;
    __syncthreads();
    float m = red[u];
    #pragma unroll
    for (int k2 = 1; k2 < 8; k2++) m = fmaxf(m, red[k2 * 33 + u]);
    __syncthreads();
    float ls = 0.f;
    for (int z = rr * 32; z < rr * 32 + 32; z++) {
        float e = __expf(Ss[z * SS_STRIDE + u] - m);
        Ss[z * SS_STRIDE + u] = e;
        ls += e;
    }
    red[rr * 33 + u] = ls;
    __syncthreads();
    if (tid < 32) {
        float ssum = 0.f;
        for (int k2 = 0; k2 < 8; k2++) ssum += red[k2 * 33 + u];
        invs[u] = 1.0f / ssum;
    }
    __syncthreads();

    // ======== O phase ========
    #pragma unroll
    for (int i = 0; i < 32; i++) acc[i] = 0.f;

    if (dir == 0) {
        // O[xi][y] = sum_z P[xi][z] * V[z][y]
        for (int zc = 0; zc < 8; zc++) {
            int z0 = zc * 32;
            const float4* V4 = (const float4*)(V + z0 * 256);
            for (int idx = tid; idx < 2048; idx += 256) {
                int zz = idx >> 6, y4 = idx & 63;
                ((float4*)(Bs + zz * BS_STRIDE))[y4] = V4[zz * 64 + y4];
            }
            __syncthreads();
            #pragma unroll 4
            for (int zz = 0; zz < 32; zz++) {
                float av[8];
                #pragma unroll
                for (int i = 0; i < 8; i++) av[i] = Ss[(z0 + zz) * SS_STRIDE + fb * 8 + i];
                float4 bv = *(const float4*)(Bs + zz * BS_STRIDE + fa * 4);
                #pragma unroll
                for (int i = 0; i < 8; i++) {
                    acc[i * 4 + 0] += av[i] * bv.x;
                    acc[i * 4 + 1] += av[i] * bv.y;
                    acc[i * 4 + 2] += av[i] * bv.z;
                    acc[i * 4 + 3] += av[i] * bv.w;
                }
            }
            __syncthreads();
        }
        float* O = g_outh + (size_t)s * HWN;
        #pragma unroll
        for (int i = 0; i < 8; i++) {
            float inv = invs[fb * 8 + i];
            float4 v4 = make_float4(acc[i * 4] * inv, acc[i * 4 + 1] * inv,
                                    acc[i * 4 + 2] * inv, acc[i * 4 + 3] * inv);
            *(float4*)(O + (t32 + fb * 8 + i) * 256 + fa * 4) = v4;
        }
    } else {
        // O'[x][yi] = sum_z V[x][z] * P[yi][z]   (writes columns t32..t32+31)
        int fg  = tid >> 3;  // 0..31 -> x fragment (8-wide)
        int fa2 = tid & 7;   // 0..7  -> yi fragment (4-wide)
        for (int zc = 0; zc < 8; zc++) {
            int z0 = zc * 32;
            for (int idx = tid; idx < 8192; idx += 256) {
                int xx = idx >> 5, zz = idx & 31;
                Bs[zz * BS_STRIDE + xx] = V[xx * 256 + z0 + zz];
            }
            __syncthreads();
            #pragma unroll 4
            for (int zz = 0; zz < 32; zz++) {
                float av[4];
                #pragma unroll
                for (int j = 0; j < 4; j++) av[j] = Ss[(z0 + zz) * SS_STRIDE + fa2 * 4 + j];
                float4 b0 = *(const float4*)(Bs + zz * BS_STRIDE + fg * 8);
                float4 b1 = *(const float4*)(Bs + zz * BS_STRIDE + fg * 8 + 4);
                float bv[8] = {b0.x, b0.y, b0.z, b0.w, b1.x, b1.y, b1.z, b1.w};
                #pragma unroll
                for (int i = 0; i < 8; i++)
                    #pragma unroll
                    for (int j = 0; j < 4; j++)
                        acc[i * 4 + j] += bv[i] * av[j];
            }
            __syncthreads();
        }
        float* O = g_outv + (size_t)s * HWN;
        float inv0 = invs[fa2 * 4], inv1 = invs[fa2 * 4 + 1];
        float inv2 = invs[fa2 * 4 + 2], inv3 = invs[fa2 * 4 + 3];
        #pragma unroll
        for (int i = 0; i < 8; i++) {
            float4 v4 = make_float4(acc[i * 4] * inv0, acc[i * 4 + 1] * inv1,
                                    acc[i * 4 + 2] * inv2, acc[i * 4 + 3] * inv3);
            *(float4*)(O + (fg * 8 + i) * 256 + t32 + fa2 * 4) = v4;
        }
    }
}

// ---------------- 7) gated fusion + 64x64 output projection ----------------
__global__ void k_fuse(const float* __restrict__ wp, const float* __restrict__ bp,
                       float* __restrict__ out) {
    __shared__ float ws[4096];
    __shared__ float bs[64];
    for (int i = threadIdx.x; i < 4096; i += 256) ws[i] = wp[i];
    if (threadIdx.x < 64) bs[threadIdx.x] = bp[threadIdx.x];
    __syncthreads();
    long long g = (long long)blockIdx.x * 256 + threadIdx.x;
    int b = (int)(g >> 16);
    int p = (int)(g & 65535);
    float cw = g_cw[b], aw = g_aw[b];
    float sr[64];
    size_t base = (size_t)b * 64 * HWN + p;
    #pragma unroll
    for (int c = 0; c < 64; c++) {
        size_t off = base + (size_t)c * HWN;
        sr[c] = cw * g_conv[off] + aw * (g_outh[off] + g_outv[off]);
    }
    for (int o = 0; o < 64; o++) {
        const float4* wr = (const float4*)(ws + o * 64);
        float acc = 0.f;
        #pragma unroll
        for (int c4 = 0; c4 < 16; c4++) {
            float4 w4 = wr[c4];
            acc += w4.x * sr[c4 * 4] + w4.y * sr[c4 * 4 + 1]
                 + w4.z * sr[c4 * 4 + 2] + w4.w * sr[c4 * 4 + 3];
        }
        out[base + (size_t)o * HWN] = bs[o] + acc;
    }
}

// ---------------- launcher ----------------
static const int ATTN_SMEM = (32 * AS_STRIDE + 32 * BS_STRIDE + 256 * SS_STRIDE + 8 * 33 + 32) * 4;

extern "C" void kernel_launch(void* const* d_in, const int* in_sizes, int n_in,
                              void* d_out, int out_size) {
    const float* x    = (const float*)d_in[0];
    const float* w3   = (const float*)d_in[1];
    const float* b3   = (const float*)d_in[2];
    const float* w5   = (const float*)d_in[3];
    const float* b5   = (const float*)d_in[4];
    const float* wqkv = (const float*)d_in[5];
    const float* scl  = (const float*)d_in[6];
    const float* g1w  = (const float*)d_in[7];
    const float* g1b  = (const float*)d_in[8];
    const float* g2w  = (const float*)d_in[9];
    const float* g2b  = (const float*)d_in[10];
    const float* wp   = (const float*)d_in[11];
    const float* bp   = (const float*)d_in[12];
    float* out = (float*)d_out;

    // one-time host-side attribute config (pre-capture on the correctness call)
    static bool configured = []() {
        cudaFuncSetAttribute(k_attn, cudaFuncAttributeMaxDynamicSharedMemorySize, ATTN_SMEM);
        return true;
    }();
    (void)configured;

    k_mean<<<256, 256>>>(x);
    k_gate<<<1, 32>>>(g1w, g1b, g2w, g2b);
    k_conv<<<65536, 256>>>(x, w3, b3, w5, b5);
    k_qkv<<<1024, 256>>>(x, wqkv);
    k_norm<<<512, 256>>>();
    k_attn<<<4096, 256, ATTN_SMEM>>>(scl);
    k_fuse<<<1024, 256>>>(wp, bp, out);
}

// round 3
// speedup vs baseline: 1.7968x; 1.7968x over previous
#include <cuda_runtime.h>
#include <math.h>
#include <stdint.h>

#define BSZ 4
#define DIM 64
#define HWN 65536          // 256*256

// ---------------- device scratch (static, allocation-free) ----------------
__device__ float g_qkv [BSZ * 192 * HWN];   // [b][o=3*64][x*256+y]
__device__ float g_conv[BSZ * DIM * HWN];
__device__ float g_outh[BSZ * DIM * HWN];
__device__ float g_outv[BSZ * DIM * HWN];
__device__ float g_gx  [BSZ * DIM];
__device__ float g_cw  [BSZ];
__device__ float g_aw  [BSZ];
__device__ float g_norm[2 * BSZ * DIM];

// ============================ helpers ============================
__device__ __forceinline__ uint32_t f2tf32(float f) {
    uint32_t u;
    asm("cvt.rna.tf32.f32 %0, %1;" : "=r"(u) : "f"(f));
    return u;
}

#define MMA8(d, a, b) \
    asm volatile("mma.sync.aligned.m16n8k8.row.col.f32.tf32.tf32.f32 " \
        "{%0,%1,%2,%3},{%4,%5,%6,%7},{%8,%9},{%0,%1,%2,%3};" \
        : "+f"((d)[0]), "+f"((d)[1]), "+f"((d)[2]), "+f"((d)[3]) \
        : "r"((a)[0]), "r"((a)[1]), "r"((a)[2]), "r"((a)[3]), \
          "r"((b)[0]), "r"((b)[1]))

// ---------------- 1) per-channel spatial mean ----------------
__global__ void k_mean(const float* __restrict__ x) {
    int bc = blockIdx.x;
    int tid = threadIdx.x;
    const float* p = x + (size_t)bc * HWN;
    float s = 0.f;
    for (int i = tid; i < HWN; i += 256) s += p[i];
    __shared__ float red[256];
    red[tid] = s; __syncthreads();
    for (int o = 128; o; o >>= 1) { if (tid < o) red[tid] += red[tid + o]; __syncthreads(); }
    if (tid == 0) g_gx[bc] = red[0] * (1.0f / HWN);
}

// ---------------- 2) gate MLP ----------------
__global__ void k_gate(const float* __restrict__ g1w, const float* __restrict__ g1b,
                       const float* __restrict__ g2w, const float* __restrict__ g2b) {
    int b = threadIdx.x;
    if (b >= BSZ) return;
    float h1[16];
    for (int j = 0; j < 16; j++) {
        float a = g1b[j];
        for (int c = 0; c < 64; c++) a += g_gx[b * 64 + c] * g1w[j * 64 + c];
        h1[j] = fmaxf(a, 0.f);
    }
    float l0 = g2b[0], l1 = g2b[1];
    for (int j = 0; j < 16; j++) { l0 += h1[j] * g2w[j]; l1 += h1[j] * g2w[16 + j]; }
    float m = fmaxf(l0, l1);
    float e0 = expf(l0 - m), e1 = expf(l1 - m);
    float inv = 1.f / (e0 + e1);
    g_cw[b] = e0 * inv;
    g_aw[b] = e1 * inv;
}

// ---------------- 3) fused depthwise 3x3 + 5x5 conv ----------------
__global__ void k_conv(const float* __restrict__ x,
                       const float* __restrict__ w3, const float* __restrict__ b3,
                       const float* __restrict__ w5, const float* __restrict__ b5) {
    long long idx = (long long)blockIdx.x * 256 + threadIdx.x;
    int bc = (int)(idx >> 16);
    int p  = (int)(idx & 65535);
    int c  = bc & 63;
    int h  = p >> 8, w = p & 255;
    __shared__ float s3[9], s5[25], sb[1];
    if (threadIdx.x < 9)  s3[threadIdx.x] = w3[c * 9 + threadIdx.x];
    if (threadIdx.x < 25) s5[threadIdx.x] = w5[c * 25 + threadIdx.x];
    if (threadIdx.x == 0) sb[0] = b3[c] + b5[c];
    __syncthreads();
    const float* xp = x + (size_t)bc * HWN;
    float acc = sb[0];
    #pragma unroll
    for (int dh = -2; dh <= 2; dh++) {
        int hh = h + dh;
        if ((unsigned)hh >= 256u) continue;
        const float* row = xp + hh * 256;
        #pragma unroll
        for (int dw = -2; dw <= 2; dw++) {
            int ww = w + dw;
            if ((unsigned)ww >= 256u) continue;
            float v = row[ww];
            acc += v * s5[(dh + 2) * 5 + (dw + 2)];
            if (dh >= -1 && dh <= 1 && dw >= -1 && dw <= 1)
                acc += v * s3[(dh + 1) * 3 + (dw + 1)];
        }
    }
    g_conv[idx] = acc;
}

// ---------------- 4) per-pixel QKV projection (192x64) ----------------
__global__ void k_qkv(const float* __restrict__ x, const float* __restrict__ wqkv) {
    __shared__ float ws[192 * 64];
    for (int i = threadIdx.x; i < 192 * 64; i += 256) ws[i] = wqkv[i];
    __syncthreads();
    long long g = (long long)blockIdx.x * 256 + threadIdx.x;
    int b = (int)(g >> 16);
    int p = (int)(g & 65535);
    float xr[64];
    const float* xp = x + (size_t)b * 64 * HWN + p;
    #pragma unroll
    for (int c = 0; c < 64; c++) xr[c] = xp[(size_t)c * HWN];
    float* outp = g_qkv + (size_t)b * 192 * HWN + p;
    for (int o = 0; o < 192; o++) {
        const float4* wr = (const float4*)(ws + o * 64);
        float acc = 0.f;
        #pragma unroll
        for (int c4 = 0; c4 < 16; c4++) {
            float4 w4 = wr[c4];
            acc += w4.x * xr[c4 * 4] + w4.y * xr[c4 * 4 + 1]
                 + w4.z * xr[c4 * 4 + 2] + w4.w * xr[c4 * 4 + 3];
        }
        outp[(size_t)o * HWN] = acc;
    }
}

// ---------------- 5) slice L2 norms ----------------
__global__ void k_norm() {
    int s2 = blockIdx.x;
    int which = s2 >> 8;
    int s = s2 & 255;
    int b = s >> 6, ch = s & 63;
    const float* p = g_qkv + ((size_t)b * 192 + which * 64 + ch) * HWN;
    float acc = 0.f;
    for (int i = threadIdx.x; i < HWN; i += 256) { float v = p[i]; acc += v * v; }
    __shared__ float red[256];
    red[threadIdx.x] = acc; __syncthreads();
    for (int o = 128; o; o >>= 1) { if (threadIdx.x < o) red[threadIdx.x] += red[threadIdx.x + o]; __syncthreads(); }
    if (threadIdx.x == 0) g_norm[s2] = fmaxf(sqrtf(red[0]), 1e-12f);
}

// ---------------- 6) mma.sync tf32 dual-axis attention ----------------
// block = (slice s, M-half, direction). 256 threads = 8 warps (2 x 4 tile grid),
// warp tile 64x64 (m16n8k8 tiles: 4 x 8, 128 accum regs).
// GEMM1: S[128,256] = A @ B1^T, smem tiles with k-chunk 32.
// softmax (exp, no max-sub; |S*alpha|<=1) -> P (tf32) in smem [128][260].
// GEMM2: O[128,256] = P @ B2^T, A-frags straight from P smem.
// dir=1 loads tiles transposed from gmem (coalesced) - no global transpose pass.

#define AS_ST 36
#define BS_ST 36
#define P_ST  260
#define S2_ST 132
#define ASO 0
#define BSO (128 * AS_ST)                 // 4608
#define PO  (BSO + 256 * BS_ST)           // 13824
#define ATTN_DYN ((PO + 256 * S2_ST) * 4) // 190464 bytes

__global__ void __launch_bounds__(256, 1) k_attn_mma(const float* __restrict__ scale) {
    extern __shared__ float dynf[];
    float* Asf = dynf + ASO;       // [128][36]
    float* Bsf = dynf + BSO;       // [256][36]
    float* Pf  = dynf + PO;        // [128][260]  (union with S2 [256][132])
    __shared__ float s_rows[4 * 128];
    __shared__ float s_inv[128];

    int tid = threadIdx.x;
    int wid = tid >> 5, lane = tid & 31;
    int gq = lane >> 2, tq = lane & 3;     // groupID, threadID-in-group
    int wm = wid & 1, wn = wid >> 1;       // 2 x 4 warp grid
    int mW = wm * 64, nW = wn * 64;

    int bid = blockIdx.x;
    int s = bid & 255, half = (bid >> 8) & 1, dir = bid >> 9;
    int b = s >> 6, ch = s & 63, hd = ch & 7;
    int m0 = half << 7;

    const float* Qp = g_qkv + ((size_t)b * 192 + ch) * HWN;
    const float* Kp = Qp + (size_t)64 * HWN;
    const float* Vp = Qp + (size_t)128 * HWN;
    float alpha = scale[hd] / (g_norm[s] * g_norm[256 + s]);

    float acc[4][8][4];
    #pragma unroll
    for (int mt = 0; mt < 4; mt++)
        #pragma unroll
        for (int nt = 0; nt < 8; nt++)
            #pragma unroll
            for (int j = 0; j < 4; j++) acc[mt][nt][j] = 0.f;

    // ======================= GEMM1 =======================
    for (int cc = 0; cc < 8; cc++) {
        int c0 = cc * 32;
        // --- load A tile [128 m][32 k] ---
        if (dir == 0) {
            for (int i = tid; i < 1024; i += 256) {       // 128 rows x 8 float4
                int r = i >> 3, q = i & 7;
                float4 v = *(const float4*)(Qp + (size_t)(m0 + r) * 256 + c0 + q * 4);
                float* d = Asf + r * AS_ST + q * 4;
                d[0] = __uint_as_float(f2tf32(v.x)); d[1] = __uint_as_float(f2tf32(v.y));
                d[2] = __uint_as_float(f2tf32(v.z)); d[3] = __uint_as_float(f2tf32(v.w));
            }
        } else {
            for (int i = tid; i < 1024; i += 256) {       // 32 k-rows x 32 float4 (m)
                int kk = i >> 5, q = i & 31;
                float4 v = *(const float4*)(Qp + (size_t)(c0 + kk) * 256 + m0 + q * 4);
                Asf[(q * 4 + 0) * AS_ST + kk] = __uint_as_float(f2tf32(v.x));
                Asf[(q * 4 + 1) * AS_ST + kk] = __uint_as_float(f2tf32(v.y));
                Asf[(q * 4 + 2) * AS_ST + kk] = __uint_as_float(f2tf32(v.z));
                Asf[(q * 4 + 3) * AS_ST + kk] = __uint_as_float(f2tf32(v.w));
            }
        }
        // --- load B tile [256 n][32 k] ---
        if (dir == 0) {
            for (int i = tid; i < 2048; i += 256) {
                int r = i >> 3, q = i & 7;
                float4 v = *(const float4*)(Kp + (size_t)r * 256 + c0 + q * 4);
                float* d = Bsf + r * BS_ST + q * 4;
                d[0] = __uint_as_float(f2tf32(v.x)); d[1] = __uint_as_float(f2tf32(v.y));
                d[2] = __uint_as_float(f2tf32(v.z)); d[3] = __uint_as_float(f2tf32(v.w));
            }
        } else {
            for (int i = tid; i < 2048; i += 256) {       // 32 k-rows x 64 float4 (n)
                int kk = i >> 6, q = i & 63;
                float4 v = *(const float4*)(Kp + (size_t)(c0 + kk) * 256 + q * 4);
                Bsf[(q * 4 + 0) * BS_ST + kk] = __uint_as_float(f2tf32(v.x));
                Bsf[(q * 4 + 1) * BS_ST + kk] = __uint_as_float(f2tf32(v.y));
                Bsf[(q * 4 + 2) * BS_ST + kk] = __uint_as_float(f2tf32(v.z));
                Bsf[(q * 4 + 3) * BS_ST + kk] = __uint_as_float(f2tf32(v.w));
            }
        }
        __syncthreads();
        #pragma unroll
        for (int ks = 0; ks < 4; ks++) {
            int k0 = ks * 8;
            uint32_t bf[8][2];
            #pragma unroll
            for (int nt = 0; nt < 8; nt++) {
                const float* bp = Bsf + (nW + nt * 8 + gq) * BS_ST + k0 + tq;
                bf[nt][0] = __float_as_uint(bp[0]);
                bf[nt][1] = __float_as_uint(bp[4]);
            }
            #pragma unroll
            for (int mt = 0; mt < 4; mt++) {
                uint32_t af[4];
                const float* a0 = Asf + (mW + mt * 16 + gq) * AS_ST + k0 + tq;
                af[0] = __float_as_uint(a0[0]);
                af[1] = __float_as_uint(a0[8 * AS_ST]);
                af[2] = __float_as_uint(a0[4]);
                af[3] = __float_as_uint(a0[8 * AS_ST + 4]);
                #pragma unroll
                for (int nt = 0; nt < 8; nt++) MMA8(acc[mt][nt], af, bf[nt]);
            }
        }
        __syncthreads();
    }

    // ======================= softmax =======================
    #pragma unroll
    for (int mt = 0; mt < 4; mt++) {
        float rs0 = 0.f, rs1 = 0.f;
        #pragma unroll
        for (int nt = 0; nt < 8; nt++) {
            #pragma unroll
            for (int j = 0; j < 4; j++) {
                float e = __expf(fminf(acc[mt][nt][j] * alpha, 80.f));
                float er = __uint_as_float(f2tf32(e));
                acc[mt][nt][j] = er;
                if (j < 2) rs0 += er; else rs1 += er;
            }
            // write P (float2: cols 2t,2t+1)
            int r0 = mW + mt * 16 + gq;
            int c = nW + nt * 8 + 2 * tq;
            *(float2*)(Pf + r0 * P_ST + c)       = make_float2(acc[mt][nt][0], acc[mt][nt][1]);
            *(float2*)(Pf + (r0 + 8) * P_ST + c) = make_float2(acc[mt][nt][2], acc[mt][nt][3]);
        }
        rs0 += __shfl_xor_sync(0xFFFFFFFFu, rs0, 1);
        rs0 += __shfl_xor_sync(0xFFFFFFFFu, rs0, 2);
        rs1 += __shfl_xor_sync(0xFFFFFFFFu, rs1, 1);
        rs1 += __shfl_xor_sync(0xFFFFFFFFu, rs1, 2);
        if (tq == 0) {
            s_rows[wn * 128 + mW + mt * 16 + gq]     = rs0;
            s_rows[wn * 128 + mW + mt * 16 + gq + 8] = rs1;
        }
    }
    __syncthreads();
    if (tid < 128)
        s_inv[tid] = 1.0f / (s_rows[tid] + s_rows[128 + tid] + s_rows[256 + tid] + s_rows[384 + tid]);

    #pragma unroll
    for (int mt = 0; mt < 4; mt++)
        #pragma unroll
        for (int nt = 0; nt < 8; nt++)
            #pragma unroll
            for (int j = 0; j < 4; j++) acc[mt][nt][j] = 0.f;
    __syncthreads();

    // ======================= GEMM2 =======================
    for (int cc = 0; cc < 8; cc++) {
        int c0 = cc * 32;
        if (dir == 1) {   // B2[n][k] = V[n][k] direct
            for (int i = tid; i < 2048; i += 256) {
                int r = i >> 3, q = i & 7;
                float4 v = *(const float4*)(Vp + (size_t)r * 256 + c0 + q * 4);
                float* d = Bsf + r * BS_ST + q * 4;
                d[0] = __uint_as_float(f2tf32(v.x)); d[1] = __uint_as_float(f2tf32(v.y));
                d[2] = __uint_as_float(f2tf32(v.z)); d[3] = __uint_as_float(f2tf32(v.w));
            }
        } else {          // B2[n][k] = V[k][n] transposed
            for (int i = tid; i < 2048; i += 256) {
                int kk = i >> 6, q = i & 63;
                float4 v = *(const float4*)(Vp + (size_t)(c0 + kk) * 256 + q * 4);
                Bsf[(q * 4 + 0) * BS_ST + kk] = __uint_as_float(f2tf32(v.x));
                Bsf[(q * 4 + 1) * BS_ST + kk] = __uint_as_float(f2tf32(v.y));
                Bsf[(q * 4 + 2) * BS_ST + kk] = __uint_as_float(f2tf32(v.z));
                Bsf[(q * 4 + 3) * BS_ST + kk] = __uint_as_float(f2tf32(v.w));
            }
        }
        __syncthreads();
        #pragma unroll
        for (int ks = 0; ks < 4; ks++) {
            int k0 = c0 + ks * 8;
            uint32_t bf[8][2];
            #pragma unroll
            for (int nt = 0; nt < 8; nt++) {
                const float* bp = Bsf + (nW + nt * 8 + gq) * BS_ST + ks * 8 + tq;
                bf[nt][0] = __float_as_uint(bp[0]);
                bf[nt][1] = __float_as_uint(bp[4]);
            }
            #pragma unroll
            for (int mt = 0; mt < 4; mt++) {
                uint32_t af[4];
                const float* a0 = Pf + (mW + mt * 16 + gq) * P_ST + k0 + tq;
                af[0] = __float_as_uint(a0[0]);
                af[1] = __float_as_uint(a0[8 * P_ST]);
                af[2] = __float_as_uint(a0[4]);
                af[3] = __float_as_uint(a0[8 * P_ST + 4]);
                #pragma unroll
                for (int nt = 0; nt < 8; nt++) MMA8(acc[mt][nt], af, bf[nt]);
            }
        }
        __syncthreads();
    }

    // ======================= epilogue =======================
    if (dir == 0) {
        // stage normalized O row-major in Pf [m][260], then coalesced store
        #pragma unroll
        for (int mt = 0; mt < 4; mt++) {
            int r0 = mW + mt * 16 + gq;
            float i0 = s_inv[r0], i1 = s_inv[r0 + 8];
            #pragma unroll
            for (int nt = 0; nt < 8; nt++) {
                int c = nW + nt * 8 + 2 * tq;
                *(float2*)(Pf + r0 * P_ST + c) =
                    make_float2(acc[mt][nt][0] * i0, acc[mt][nt][1] * i0);
                *(float2*)(Pf + (r0 + 8) * P_ST + c) =
                    make_float2(acc[mt][nt][2] * i1, acc[mt][nt][3] * i1);
            }
        }
        __syncthreads();
        float* O = g_outh + (size_t)s * HWN;
        for (int i = tid; i < 8192; i += 256) {
            int r = i >> 6, q = i & 63;
            *(float4*)(O + (size_t)(m0 + r) * 256 + q * 4) =
                *(const float4*)(Pf + r * P_ST + q * 4);
        }
    } else {
        // stage normalized O transposed: S2[n][m] stride 132, then coalesced store
        float* S2 = Pf;
        #pragma unroll
        for (int mt = 0; mt < 4; mt++) {
            int r0 = mW + mt * 16 + gq;
            float i0 = s_inv[r0], i1 = s_inv[r0 + 8];
            #pragma unroll
            for (int nt = 0; nt < 8; nt++) {
                int c = nW + nt * 8 + 2 * tq;
                S2[c * S2_ST + r0]           = acc[mt][nt][0] * i0;
                S2[(c + 1) * S2_ST + r0]     = acc[mt][nt][1] * i0;
                S2[c * S2_ST + r0 + 8]       = acc[mt][nt][2] * i1;
                S2[(c + 1) * S2_ST + r0 + 8] = acc[mt][nt][3] * i1;
            }
        }
        __syncthreads();
        float* O = g_outv + (size_t)s * HWN;
        for (int i = tid; i < 8192; i += 256) {
            int n = i >> 5, q = i & 31;
            *(float4*)(O + (size_t)n * 256 + m0 + q * 4) =
                *(const float4*)(S2 + n * S2_ST + q * 4);
        }
    }
}

// ---------------- 7) gated fusion + 64x64 output projection ----------------
__global__ void k_fuse(const float* __restrict__ wp, const float* __restrict__ bp,
                       float* __restrict__ out) {
    __shared__ float ws[4096];
    __shared__ float bs[64];
    for (int i = threadIdx.x; i < 4096; i += 256) ws[i] = wp[i];
    if (threadIdx.x < 64) bs[threadIdx.x] = bp[threadIdx.x];
    __syncthreads();
    long long g = (long long)blockIdx.x * 256 + threadIdx.x;
    int b = (int)(g >> 16);
    int p = (int)(g & 65535);
    float cw = g_cw[b], aw = g_aw[b];
    float sr[64];
    size_t base = (size_t)b * 64 * HWN + p;
    #pragma unroll
    for (int c = 0; c < 64; c++) {
        size_t off = base + (size_t)c * HWN;
        sr[c] = cw * g_conv[off] + aw * (g_outh[off] + g_outv[off]);
    }
    for (int o = 0; o < 64; o++) {
        const float4* wr = (const float4*)(ws + o * 64);
        float acc = 0.f;
        #pragma unroll
        for (int c4 = 0; c4 < 16; c4++) {
            float4 w4 = wr[c4];
            acc += w4.x * sr[c4 * 4] + w4.y * sr[c4 * 4 + 1]
                 + w4.z * sr[c4 * 4 + 2] + w4.w * sr[c4 * 4 + 3];
        }
        out[base + (size_t)o * HWN] = bs[o] + acc;
    }
}

// ---------------- launcher ----------------
extern "C" void kernel_launch(void* const* d_in, const int* in_sizes, int n_in,
                              void* d_out, int out_size) {
    const float* x    = (const float*)d_in[0];
    const float* w3   = (const float*)d_in[1];
    const float* b3   = (const float*)d_in[2];
    const float* w5   = (const float*)d_in[3];
    const float* b5   = (const float*)d_in[4];
    const float* wqkv = (const float*)d_in[5];
    const float* scl  = (const float*)d_in[6];
    const float* g1w  = (const float*)d_in[7];
    const float* g1b  = (const float*)d_in[8];
    const float* g2w  = (const float*)d_in[9];
    const float* g2b  = (const float*)d_in[10];
    const float* wp   = (const float*)d_in[11];
    const float* bp   = (const float*)d_in[12];
    float* out = (float*)d_out;

    static bool configured = []() {
        cudaFuncSetAttribute(k_attn_mma, cudaFuncAttributeMaxDynamicSharedMemorySize, ATTN_DYN);
        return true;
    }();
    (void)configured;

    k_mean<<<256, 256>>>(x);
    k_gate<<<1, 32>>>(g1w, g1b, g2w, g2b);
    k_conv<<<65536, 256>>>(x, w3, b3, w5, b5);
    k_qkv<<<1024, 256>>>(x, wqkv);
    k_norm<<<512, 256>>>();
    k_attn_mma<<<1024, 256, ATTN_DYN>>>(scl);
    k_fuse<<<1024, 256>>>(wp, bp, out);
}

// round 4
// speedup vs baseline: 2.2014x; 1.2252x over previous
#include <cuda_runtime.h>
#include <math.h>
#include <stdint.h>

#define BSZ 4
#define DIM 64
#define HWN 65536          // 256*256

// ---------------- device scratch (static, allocation-free) ----------------
__device__ float g_qkv [BSZ * 192 * HWN];   // [b][o=3*64][x*256+y]
__device__ float g_conv[BSZ * DIM * HWN];
__device__ float g_outh[BSZ * DIM * HWN];
__device__ float g_outv[BSZ * DIM * HWN];
__device__ float g_gx  [BSZ * DIM];
__device__ float g_cw  [BSZ];
__device__ float g_aw  [BSZ];
__device__ float g_norm[2 * BSZ * DIM];

// ============================ helpers ============================
__device__ __forceinline__ uint32_t f2tf32(float f) {
    uint32_t u;
    asm("cvt.rna.tf32.f32 %0, %1;" : "=r"(u) : "f"(f));
    return u;
}

#define MMA8(d, a, b) \
    asm volatile("mma.sync.aligned.m16n8k8.row.col.f32.tf32.tf32.f32 " \
        "{%0,%1,%2,%3},{%4,%5,%6,%7},{%8,%9},{%0,%1,%2,%3};" \
        : "+f"((d)[0]), "+f"((d)[1]), "+f"((d)[2]), "+f"((d)[3]) \
        : "r"((a)[0]), "r"((a)[1]), "r"((a)[2]), "r"((a)[3]), \
          "r"((b)[0]), "r"((b)[1]))

// ---------------- 1) per-channel spatial mean ----------------
__global__ void k_mean(const float* __restrict__ x) {
    int bc = blockIdx.x;
    int tid = threadIdx.x;
    const float* p = x + (size_t)bc * HWN;
    float s = 0.f;
    for (int i = tid; i < HWN; i += 256) s += p[i];
    __shared__ float red[256];
    red[tid] = s; __syncthreads();
    for (int o = 128; o; o >>= 1) { if (tid < o) red[tid] += red[tid + o]; __syncthreads(); }
    if (tid == 0) g_gx[bc] = red[0] * (1.0f / HWN);
}

// ---------------- 2) gate MLP ----------------
__global__ void k_gate(const float* __restrict__ g1w, const float* __restrict__ g1b,
                       const float* __restrict__ g2w, const float* __restrict__ g2b) {
    int b = threadIdx.x;
    if (b >= BSZ) return;
    float h1[16];
    for (int j = 0; j < 16; j++) {
        float a = g1b[j];
        for (int c = 0; c < 64; c++) a += g_gx[b * 64 + c] * g1w[j * 64 + c];
        h1[j] = fmaxf(a, 0.f);
    }
    float l0 = g2b[0], l1 = g2b[1];
    for (int j = 0; j < 16; j++) { l0 += h1[j] * g2w[j]; l1 += h1[j] * g2w[16 + j]; }
    float m = fmaxf(l0, l1);
    float e0 = expf(l0 - m), e1 = expf(l1 - m);
    float inv = 1.f / (e0 + e1);
    g_cw[b] = e0 * inv;
    g_aw[b] = e1 * inv;
}

// ---------------- 3) tiled fused depthwise 3x3+5x5 conv ----------------
// block = (bc, 32x32 tile). 36x36 halo tile in smem; 3x3 taps folded into 5x5.
__global__ void __launch_bounds__(256) k_conv_t(const float* __restrict__ x,
                       const float* __restrict__ w3, const float* __restrict__ b3,
                       const float* __restrict__ w5, const float* __restrict__ b5) {
    int bid = blockIdx.x;
    int bc = bid >> 6;
    int tile = bid & 63;
    int th = (tile >> 3) * 32, tw = (tile & 7) * 32;
    int c = bc & 63;
    int tid = threadIdx.x;

    __shared__ float t[36 * 36];
    __shared__ float wc[25];
    __shared__ float sb[1];
    if (tid < 25) {
        float w = w5[c * 25 + tid];
        int dh = tid / 5 - 2, dw = tid % 5 - 2;
        if (dh >= -1 && dh <= 1 && dw >= -1 && dw <= 1)
            w += w3[c * 9 + (dh + 1) * 3 + (dw + 1)];
        wc[tid] = w;
    }
    if (tid == 25) sb[0] = b3[c] + b5[c];

    const float* xp = x + (size_t)bc * HWN;
    for (int i = tid; i < 1296; i += 256) {
        int r = i / 36, col = i - r * 36;
        int gh = th - 2 + r, gw = tw - 2 + col;
        float v = 0.f;
        if ((unsigned)gh < 256u && (unsigned)gw < 256u) v = xp[gh * 256 + gw];
        t[i] = v;
    }
    __syncthreads();

    int oh = tid >> 3, ow4 = (tid & 7) * 4;
    float bias = sb[0];
    float a0 = bias, a1 = bias, a2 = bias, a3 = bias;
    #pragma unroll
    for (int dh = 0; dh < 5; dh++) {
        const float* row = t + (oh + dh) * 36 + ow4;
        float r0 = row[0], r1 = row[1], r2 = row[2], r3 = row[3];
        float r4 = row[4], r5 = row[5], r6 = row[6], r7 = row[7];
        const float* w = wc + dh * 5;
        float w0 = w[0], w1 = w[1], w2 = w[2], w3v = w[3], w4 = w[4];
        a0 += r0 * w0 + r1 * w1 + r2 * w2 + r3 * w3v + r4 * w4;
        a1 += r1 * w0 + r2 * w1 + r3 * w2 + r4 * w3v + r5 * w4;
        a2 += r2 * w0 + r3 * w1 + r4 * w2 + r5 * w3v + r6 * w4;
        a3 += r3 * w0 + r4 * w1 + r5 * w2 + r6 * w3v + r7 * w4;
    }
    *(float4*)(g_conv + (size_t)bc * HWN + (th + oh) * 256 + tw + ow4) =
        make_float4(a0, a1, a2, a3);
}

// ---------------- 4) QKV projection via tf32 mma ----------------
// block: 128 pixels x 192 outputs, K=64. 8 warps (2m x 4n), warp tile 64x48.
#define QK_ST 68
#define QK_AS 0
#define QK_WS (128 * QK_ST)
#define QKV_DYN ((128 * QK_ST + 192 * QK_ST) * 4)   // 87040 bytes

__global__ void __launch_bounds__(256, 2) k_qkv_mma(const float* __restrict__ x,
                                                    const float* __restrict__ wqkv) {
    extern __shared__ float qs[];
    float* As = qs + QK_AS;    // [128 m][68]
    float* Ws = qs + QK_WS;    // [192 n][68]

    int tid = threadIdx.x;
    int wid = tid >> 5, lane = tid & 31;
    int gq = lane >> 2, tq = lane & 3;
    int wm = wid & 1, wn = wid >> 1;
    int mW = wm * 64, nW = wn * 48;

    int bid = blockIdx.x;
    int b = bid >> 9;
    int p0 = (bid & 511) << 7;
    const float* xb = x + (size_t)b * 64 * HWN;

    // load W [192][64] -> Ws (tf32-rounded)
    for (int i = tid; i < 192 * 16; i += 256) {
        int o = i >> 4, c4 = i & 15;
        float4 v = *(const float4*)(wqkv + o * 64 + c4 * 4);
        float* d = Ws + o * QK_ST + c4 * 4;
        d[0] = __uint_as_float(f2tf32(v.x)); d[1] = __uint_as_float(f2tf32(v.y));
        d[2] = __uint_as_float(f2tf32(v.z)); d[3] = __uint_as_float(f2tf32(v.w));
    }
    // load A: x[c][p0+j] -> As[j][c] (transpose, tf32-rounded)
    for (int i = tid; i < 8192; i += 256) {
        int c = i >> 7, j = i & 127;
        As[j * QK_ST + c] = __uint_as_float(f2tf32(xb[(size_t)c * HWN + p0 + j]));
    }
    __syncthreads();

    float acc[4][6][4];
    #pragma unroll
    for (int mt = 0; mt < 4; mt++)
        #pragma unroll
        for (int nt = 0; nt < 6; nt++)
            #pragma unroll
            for (int j = 0; j < 4; j++) acc[mt][nt][j] = 0.f;

    #pragma unroll
    for (int ks = 0; ks < 8; ks++) {
        int k0 = ks * 8;
        uint32_t bf[6][2];
        #pragma unroll
        for (int nt = 0; nt < 6; nt++) {
            const float* bp = Ws + (nW + nt * 8 + gq) * QK_ST + k0 + tq;
            bf[nt][0] = __float_as_uint(bp[0]);
            bf[nt][1] = __float_as_uint(bp[4]);
        }
        #pragma unroll
        for (int mt = 0; mt < 4; mt++) {
            uint32_t af[4];
            const float* a0 = As + (mW + mt * 16 + gq) * QK_ST + k0 + tq;
            af[0] = __float_as_uint(a0[0]);
            af[1] = __float_as_uint(a0[8 * QK_ST]);
            af[2] = __float_as_uint(a0[4]);
            af[3] = __float_as_uint(a0[8 * QK_ST + 4]);
            #pragma unroll
            for (int nt = 0; nt < 6; nt++) MMA8(acc[mt][nt], af, bf[nt]);
        }
    }
    __syncthreads();

    // stage + coalesced store, two passes of 96 o-rows ([96][132] reuses As/Ws)
    float* S = qs;
    float* outb = g_qkv + (size_t)b * 192 * HWN + p0;
    #pragma unroll
    for (int pass = 0; pass < 2; pass++) {
        if ((wn >> 1) == pass) {
            int ob = nW - pass * 96;
            #pragma unroll
            for (int mt = 0; mt < 4; mt++) {
                int m = mW + mt * 16 + gq;
                #pragma unroll
                for (int nt = 0; nt < 6; nt++) {
                    int ol = ob + nt * 8 + 2 * tq;
                    S[ol * 132 + m]           = acc[mt][nt][0];
                    S[(ol + 1) * 132 + m]     = acc[mt][nt][1];
                    S[ol * 132 + m + 8]       = acc[mt][nt][2];
                    S[(ol + 1) * 132 + m + 8] = acc[mt][nt][3];
                }
            }
        }
        __syncthreads();
        for (int i = tid; i < 96 * 32; i += 256) {
            int row = i >> 5, q = i & 31;
            *(float4*)(outb + (size_t)(pass * 96 + row) * HWN + q * 4) =
                *(const float4*)(S + row * 132 + q * 4);
        }
        __syncthreads();
    }
}

// ---------------- 5) slice L2 norms ----------------
__global__ void k_norm() {
    int s2 = blockIdx.x;
    int which = s2 >> 8;
    int s = s2 & 255;
    int b = s >> 6, ch = s & 63;
    const float* p = g_qkv + ((size_t)b * 192 + which * 64 + ch) * HWN;
    float acc = 0.f;
    for (int i = threadIdx.x; i < HWN; i += 256) { float v = p[i]; acc += v * v; }
    __shared__ float red[256];
    red[threadIdx.x] = acc; __syncthreads();
    for (int o = 128; o; o >>= 1) { if (threadIdx.x < o) red[threadIdx.x] += red[threadIdx.x + o]; __syncthreads(); }
    if (threadIdx.x == 0) g_norm[s2] = fmaxf(sqrtf(red[0]), 1e-12f);
}

// ---------------- 6) mma.sync tf32 dual-axis attention (unchanged) ----------------
#define AS_ST 36
#define BS_ST 36
#define P_ST  260
#define S2_ST 132
#define ASO 0
#define BSO (128 * AS_ST)
#define PO  (BSO + 256 * BS_ST)
#define ATTN_DYN ((PO + 256 * S2_ST) * 4)

__global__ void __launch_bounds__(256, 1) k_attn_mma(const float* __restrict__ scale) {
    extern __shared__ float dynf[];
    float* Asf = dynf + ASO;
    float* Bsf = dynf + BSO;
    float* Pf  = dynf + PO;
    __shared__ float s_rows[4 * 128];
    __shared__ float s_inv[128];

    int tid = threadIdx.x;
    int wid = tid >> 5, lane = tid & 31;
    int gq = lane >> 2, tq = lane & 3;
    int wm = wid & 1, wn = wid >> 1;
    int mW = wm * 64, nW = wn * 64;

    int bid = blockIdx.x;
    int s = bid & 255, half = (bid >> 8) & 1, dir = bid >> 9;
    int b = s >> 6, ch = s & 63, hd = ch & 7;
    int m0 = half << 7;

    const float* Qp = g_qkv + ((size_t)b * 192 + ch) * HWN;
    const float* Kp = Qp + (size_t)64 * HWN;
    const float* Vp = Qp + (size_t)128 * HWN;
    float alpha = scale[hd] / (g_norm[s] * g_norm[256 + s]);

    float acc[4][8][4];
    #pragma unroll
    for (int mt = 0; mt < 4; mt++)
        #pragma unroll
        for (int nt = 0; nt < 8; nt++)
            #pragma unroll
            for (int j = 0; j < 4; j++) acc[mt][nt][j] = 0.f;

    // ======================= GEMM1 =======================
    for (int cc = 0; cc < 8; cc++) {
        int c0 = cc * 32;
        if (dir == 0) {
            for (int i = tid; i < 1024; i += 256) {
                int r = i >> 3, q = i & 7;
                float4 v = *(const float4*)(Qp + (size_t)(m0 + r) * 256 + c0 + q * 4);
                float* d = Asf + r * AS_ST + q * 4;
                d[0] = __uint_as_float(f2tf32(v.x)); d[1] = __uint_as_float(f2tf32(v.y));
                d[2] = __uint_as_float(f2tf32(v.z)); d[3] = __uint_as_float(f2tf32(v.w));
            }
        } else {
            for (int i = tid; i < 1024; i += 256) {
                int kk = i >> 5, q = i & 31;
                float4 v = *(const float4*)(Qp + (size_t)(c0 + kk) * 256 + m0 + q * 4);
                Asf[(q * 4 + 0) * AS_ST + kk] = __uint_as_float(f2tf32(v.x));
                Asf[(q * 4 + 1) * AS_ST + kk] = __uint_as_float(f2tf32(v.y));
                Asf[(q * 4 + 2) * AS_ST + kk] = __uint_as_float(f2tf32(v.z));
                Asf[(q * 4 + 3) * AS_ST + kk] = __uint_as_float(f2tf32(v.w));
            }
        }
        if (dir == 0) {
            for (int i = tid; i < 2048; i += 256) {
                int r = i >> 3, q = i & 7;
                float4 v = *(const float4*)(Kp + (size_t)r * 256 + c0 + q * 4);
                float* d = Bsf + r * BS_ST + q * 4;
                d[0] = __uint_as_float(f2tf32(v.x)); d[1] = __uint_as_float(f2tf32(v.y));
                d[2] = __uint_as_float(f2tf32(v.z)); d[3] = __uint_as_float(f2tf32(v.w));
            }
        } else {
            for (int i = tid; i < 2048; i += 256) {
                int kk = i >> 6, q = i & 63;
                float4 v = *(const float4*)(Kp + (size_t)(c0 + kk) * 256 + q * 4);
                Bsf[(q * 4 + 0) * BS_ST + kk] = __uint_as_float(f2tf32(v.x));
                Bsf[(q * 4 + 1) * BS_ST + kk] = __uint_as_float(f2tf32(v.y));
                Bsf[(q * 4 + 2) * BS_ST + kk] = __uint_as_float(f2tf32(v.z));
                Bsf[(q * 4 + 3) * BS_ST + kk] = __uint_as_float(f2tf32(v.w));
            }
        }
        __syncthreads();
        #pragma unroll
        for (int ks = 0; ks < 4; ks++) {
            int k0 = ks * 8;
            uint32_t bf[8][2];
            #pragma unroll
            for (int nt = 0; nt < 8; nt++) {
                const float* bp = Bsf + (nW + nt * 8 + gq) * BS_ST + k0 + tq;
                bf[nt][0] = __float_as_uint(bp[0]);
                bf[nt][1] = __float_as_uint(bp[4]);
            }
            #pragma unroll
            for (int mt = 0; mt < 4; mt++) {
                uint32_t af[4];
                const float* a0 = Asf + (mW + mt * 16 + gq) * AS_ST + k0 + tq;
                af[0] = __float_as_uint(a0[0]);
                af[1] = __float_as_uint(a0[8 * AS_ST]);
                af[2] = __float_as_uint(a0[4]);
                af[3] = __float_as_uint(a0[8 * AS_ST + 4]);
                #pragma unroll
                for (int nt = 0; nt < 8; nt++) MMA8(acc[mt][nt], af, bf[nt]);
            }
        }
        __syncthreads();
    }

    // ======================= softmax =======================
    #pragma unroll
    for (int mt = 0; mt < 4; mt++) {
        float rs0 = 0.f, rs1 = 0.f;
        #pragma unroll
        for (int nt = 0; nt < 8; nt++) {
            #pragma unroll
            for (int j = 0; j < 4; j++) {
                float e = __expf(fminf(acc[mt][nt][j] * alpha, 80.f));
                float er = __uint_as_float(f2tf32(e));
                acc[mt][nt][j] = er;
                if (j < 2) rs0 += er; else rs1 += er;
            }
            int r0 = mW + mt * 16 + gq;
            int c = nW + nt * 8 + 2 * tq;
            *(float2*)(Pf + r0 * P_ST + c)       = make_float2(acc[mt][nt][0], acc[mt][nt][1]);
            *(float2*)(Pf + (r0 + 8) * P_ST + c) = make_float2(acc[mt][nt][2], acc[mt][nt][3]);
        }
        rs0 += __shfl_xor_sync(0xFFFFFFFFu, rs0, 1);
        rs0 += __shfl_xor_sync(0xFFFFFFFFu, rs0, 2);
        rs1 += __shfl_xor_sync(0xFFFFFFFFu, rs1, 1);
        rs1 += __shfl_xor_sync(0xFFFFFFFFu, rs1, 2);
        if (tq == 0) {
            s_rows[wn * 128 + mW + mt * 16 + gq]     = rs0;
            s_rows[wn * 128 + mW + mt * 16 + gq + 8] = rs1;
        }
    }
    __syncthreads();
    if (tid < 128)
        s_inv[tid] = 1.0f / (s_rows[tid] + s_rows[128 + tid] + s_rows[256 + tid] + s_rows[384 + tid]);

    #pragma unroll
    for (int mt = 0; mt < 4; mt++)
        #pragma unroll
        for (int nt = 0; nt < 8; nt++)
            #pragma unroll
            for (int j = 0; j < 4; j++) acc[mt][nt][j] = 0.f;
    __syncthreads();

    // ======================= GEMM2 =======================
    for (int cc = 0; cc < 8; cc++) {
        int c0 = cc * 32;
        if (dir == 1) {
            for (int i = tid; i < 2048; i += 256) {
                int r = i >> 3, q = i & 7;
                float4 v = *(const float4*)(Vp + (size_t)r * 256 + c0 + q * 4);
                float* d = Bsf + r * BS_ST + q * 4;
                d[0] = __uint_as_float(f2tf32(v.x)); d[1] = __uint_as_float(f2tf32(v.y));
                d[2] = __uint_as_float(f2tf32(v.z)); d[3] = __uint_as_float(f2tf32(v.w));
            }
        } else {
            for (int i = tid; i < 2048; i += 256) {
                int kk = i >> 6, q = i & 63;
                float4 v = *(const float4*)(Vp + (size_t)(c0 + kk) * 256 + q * 4);
                Bsf[(q * 4 + 0) * BS_ST + kk] = __uint_as_float(f2tf32(v.x));
                Bsf[(q * 4 + 1) * BS_ST + kk] = __uint_as_float(f2tf32(v.y));
                Bsf[(q * 4 + 2) * BS_ST + kk] = __uint_as_float(f2tf32(v.z));
                Bsf[(q * 4 + 3) * BS_ST + kk] = __uint_as_float(f2tf32(v.w));
            }
        }
        __syncthreads();
        #pragma unroll
        for (int ks = 0; ks < 4; ks++) {
            int k0 = c0 + ks * 8;
            uint32_t bf[8][2];
            #pragma unroll
            for (int nt = 0; nt < 8; nt++) {
                const float* bp = Bsf + (nW + nt * 8 + gq) * BS_ST + ks * 8 + tq;
                bf[nt][0] = __float_as_uint(bp[0]);
                bf[nt][1] = __float_as_uint(bp[4]);
            }
            #pragma unroll
            for (int mt = 0; mt < 4; mt++) {
                uint32_t af[4];
                const float* a0 = Pf + (mW + mt * 16 + gq) * P_ST + k0 + tq;
                af[0] = __float_as_uint(a0[0]);
                af[1] = __float_as_uint(a0[8 * P_ST]);
                af[2] = __float_as_uint(a0[4]);
                af[3] = __float_as_uint(a0[8 * P_ST + 4]);
                #pragma unroll
                for (int nt = 0; nt < 8; nt++) MMA8(acc[mt][nt], af, bf[nt]);
            }
        }
        __syncthreads();
    }

    // ======================= epilogue =======================
    if (dir == 0) {
        #pragma unroll
        for (int mt = 0; mt < 4; mt++) {
            int r0 = mW + mt * 16 + gq;
            float i0 = s_inv[r0], i1 = s_inv[r0 + 8];
            #pragma unroll
            for (int nt = 0; nt < 8; nt++) {
                int c = nW + nt * 8 + 2 * tq;
                *(float2*)(Pf + r0 * P_ST + c) =
                    make_float2(acc[mt][nt][0] * i0, acc[mt][nt][1] * i0);
                *(float2*)(Pf + (r0 + 8) * P_ST + c) =
                    make_float2(acc[mt][nt][2] * i1, acc[mt][nt][3] * i1);
            }
        }
        __syncthreads();
        float* O = g_outh + (size_t)s * HWN;
        for (int i = tid; i < 8192; i += 256) {
            int r = i >> 6, q = i & 63;
            *(float4*)(O + (size_t)(m0 + r) * 256 + q * 4) =
                *(const float4*)(Pf + r * P_ST + q * 4);
        }
    } else {
        float* S2 = Pf;
        #pragma unroll
        for (int mt = 0; mt < 4; mt++) {
            int r0 = mW + mt * 16 + gq;
            float i0 = s_inv[r0], i1 = s_inv[r0 + 8];
            #pragma unroll
            for (int nt = 0; nt < 8; nt++) {
                int c = nW + nt * 8 + 2 * tq;
                S2[c * S2_ST + r0]           = acc[mt][nt][0] * i0;
                S2[(c + 1) * S2_ST + r0]     = acc[mt][nt][1] * i0;
                S2[c * S2_ST + r0 + 8]       = acc[mt][nt][2] * i1;
                S2[(c + 1) * S2_ST + r0 + 8] = acc[mt][nt][3] * i1;
            }
        }
        __syncthreads();
        float* O = g_outv + (size_t)s * HWN;
        for (int i = tid; i < 8192; i += 256) {
            int n = i >> 5, q = i & 31;
            *(float4*)(O + (size_t)n * 256 + m0 + q * 4) =
                *(const float4*)(S2 + n * S2_ST + q * 4);
        }
    }
}

// ---------------- 7) gated fusion + 64x64 output projection ----------------
__global__ void k_fuse(const float* __restrict__ wp, const float* __restrict__ bp,
                       float* __restrict__ out) {
    __shared__ float ws[4096];
    __shared__ float bs[64];
    for (int i = threadIdx.x; i < 4096; i += 256) ws[i] = wp[i];
    if (threadIdx.x < 64) bs[threadIdx.x] = bp[threadIdx.x];
    __syncthreads();
    long long g = (long long)blockIdx.x * 256 + threadIdx.x;
    int b = (int)(g >> 16);
    int p = (int)(g & 65535);
    float cw = g_cw[b], aw = g_aw[b];
    float sr[64];
    size_t base = (size_t)b * 64 * HWN + p;
    #pragma unroll
    for (int c = 0; c < 64; c++) {
        size_t off = base + (size_t)c * HWN;
        sr[c] = cw * g_conv[off] + aw * (g_outh[off] + g_outv[off]);
    }
    for (int o = 0; o < 64; o++) {
        const float4* wr = (const float4*)(ws + o * 64);
        float acc = 0.f;
        #pragma unroll
        for (int c4 = 0; c4 < 16; c4++) {
            float4 w4 = wr[c4];
            acc += w4.x * sr[c4 * 4] + w4.y * sr[c4 * 4 + 1]
                 + w4.z * sr[c4 * 4 + 2] + w4.w * sr[c4 * 4 + 3];
        }
        out[base + (size_t)o * HWN] = bs[o] + acc;
    }
}

// ---------------- launcher ----------------
extern "C" void kernel_launch(void* const* d_in, const int* in_sizes, int n_in,
                              void* d_out, int out_size) {
    const float* x    = (const float*)d_in[0];
    const float* w3   = (const float*)d_in[1];
    const float* b3   = (const float*)d_in[2];
    const float* w5   = (const float*)d_in[3];
    const float* b5   = (const float*)d_in[4];
    const float* wqkv = (const float*)d_in[5];
    const float* scl  = (const float*)d_in[6];
    const float* g1w  = (const float*)d_in[7];
    const float* g1b  = (const float*)d_in[8];
    const float* g2w  = (const float*)d_in[9];
    const float* g2b  = (const float*)d_in[10];
    const float* wp   = (const float*)d_in[11];
    const float* bp   = (const float*)d_in[12];
    float* out = (float*)d_out;

    static bool configured = []() {
        cudaFuncSetAttribute(k_attn_mma, cudaFuncAttributeMaxDynamicSharedMemorySize, ATTN_DYN);
        cudaFuncSetAttribute(k_qkv_mma, cudaFuncAttributeMaxDynamicSharedMemorySize, QKV_DYN);
        return true;
    }();
    (void)configured;

    k_mean<<<256, 256>>>(x);
    k_gate<<<1, 32>>>(g1w, g1b, g2w, g2b);
    k_conv_t<<<16384, 256>>>(x, w3, b3, w5, b5);
    k_qkv_mma<<<2048, 256, QKV_DYN>>>(x, wqkv);
    k_norm<<<512, 256>>>();
    k_attn_mma<<<1024, 256, ATTN_DYN>>>(scl);
    k_fuse<<<1024, 256>>>(wp, bp, out);
}

// round 5
// speedup vs baseline: 3.5999x; 1.6353x over previous
#include <cuda_runtime.h>
#include <cuda_fp16.h>
#include <math.h>
#include <stdint.h>

#define BSZ 4
#define DIM 64
#define HWN 65536          // 256*256

// ---------------- device scratch (static, allocation-free) ----------------
__device__ __align__(16) __half g_hA[BSZ * 192 * HWN];   // qkv fp16, [slice][x*256+y]
__device__ __align__(16) __half g_hT[BSZ * 192 * HWN];   // fp16 transposed [y*256+x]
__device__ float g_conv[BSZ * DIM * HWN];
__device__ float g_outh[BSZ * DIM * HWN];
__device__ float g_outv[BSZ * DIM * HWN];
__device__ float g_xsum[BSZ * DIM];
__device__ float g_cw  [BSZ];
__device__ float g_aw  [BSZ];
__device__ float g_sq  [2 * BSZ * DIM];     // [0..255]=sum q^2, [256..511]=sum k^2

// ============================ helpers ============================
__device__ __forceinline__ uint32_t f2tf32(float f) {
    uint32_t u;
    asm("cvt.rna.tf32.f32 %0, %1;" : "=r"(u) : "f"(f));
    return u;
}

#define MMA8(d, a, b) \
    asm volatile("mma.sync.aligned.m16n8k8.row.col.f32.tf32.tf32.f32 " \
        "{%0,%1,%2,%3},{%4,%5,%6,%7},{%8,%9},{%0,%1,%2,%3};" \
        : "+f"((d)[0]), "+f"((d)[1]), "+f"((d)[2]), "+f"((d)[3]) \
        : "r"((a)[0]), "r"((a)[1]), "r"((a)[2]), "r"((a)[3]), \
          "r"((b)[0]), "r"((b)[1]))

#define MMA16(d, a, b) \
    asm volatile("mma.sync.aligned.m16n8k16.row.col.f32.f16.f16.f32 " \
        "{%0,%1,%2,%3},{%4,%5,%6,%7},{%8,%9},{%0,%1,%2,%3};" \
        : "+f"((d)[0]), "+f"((d)[1]), "+f"((d)[2]), "+f"((d)[3]) \
        : "r"((a)[0]), "r"((a)[1]), "r"((a)[2]), "r"((a)[3]), \
          "r"((b)[0]), "r"((b)[1]))

__device__ __forceinline__ uint32_t h2u(__half2 h) {
    return *reinterpret_cast<uint32_t*>(&h);
}

// ---------------- 0) zero accumulators ----------------
__global__ void k_zero() {
    int t = threadIdx.x;
    if (t < 256) g_xsum[t] = 0.f;
    g_sq[t] = 0.f; g_sq[t + 256] = 0.f;
}

// ---------------- 1) gate MLP (runs after conv; uses g_xsum) ----------------
__global__ void k_gate(const float* __restrict__ g1w, const float* __restrict__ g1b,
                       const float* __restrict__ g2w, const float* __restrict__ g2b) {
    int b = threadIdx.x;
    if (b >= BSZ) return;
    float gx[64];
    for (int c = 0; c < 64; c++) gx[c] = g_xsum[b * 64 + c] * (1.0f / HWN);
    float h1[16];
    for (int j = 0; j < 16; j++) {
        float a = g1b[j];
        for (int c = 0; c < 64; c++) a += gx[c] * g1w[j * 64 + c];
        h1[j] = fmaxf(a, 0.f);
    }
    float l0 = g2b[0], l1 = g2b[1];
    for (int j = 0; j < 16; j++) { l0 += h1[j] * g2w[j]; l1 += h1[j] * g2w[16 + j]; }
    float m = fmaxf(l0, l1);
    float e0 = expf(l0 - m), e1 = expf(l1 - m);
    float inv = 1.f / (e0 + e1);
    g_cw[b] = e0 * inv;
    g_aw[b] = e1 * inv;
}

// ---------------- 2) tiled fused depthwise conv + channel-mean ----------------
__global__ void __launch_bounds__(256) k_conv_t(const float* __restrict__ x,
                       const float* __restrict__ w3, const float* __restrict__ b3,
                       const float* __restrict__ w5, const float* __restrict__ b5) {
    int bid = blockIdx.x;
    int bc = bid >> 6;
    int tile = bid & 63;
    int th = (tile >> 3) * 32, tw = (tile & 7) * 32;
    int c = bc & 63;
    int tid = threadIdx.x;

    __shared__ float t[36 * 36];
    __shared__ float wc[25];
    __shared__ float sb[1];
    __shared__ float spart[8];
    if (tid < 25) {
        float w = w5[c * 25 + tid];
        int dh = tid / 5 - 2, dw = tid % 5 - 2;
        if (dh >= -1 && dh <= 1 && dw >= -1 && dw <= 1)
            w += w3[c * 9 + (dh + 1) * 3 + (dw + 1)];
        wc[tid] = w;
    }
    if (tid == 25) sb[0] = b3[c] + b5[c];

    const float* xp = x + (size_t)bc * HWN;
    for (int i = tid; i < 1296; i += 256) {
        int r = i / 36, col = i - r * 36;
        int gh = th - 2 + r, gw = tw - 2 + col;
        float v = 0.f;
        if ((unsigned)gh < 256u && (unsigned)gw < 256u) v = xp[gh * 256 + gw];
        t[i] = v;
    }
    __syncthreads();

    int oh = tid >> 3, ow4 = (tid & 7) * 4;
    // channel mean partial: interior values owned by this thread
    {
        const float* rp = t + (oh + 2) * 36 + ow4 + 2;
        float xs = rp[0] + rp[1] + rp[2] + rp[3];
        #pragma unroll
        for (int off = 16; off; off >>= 1) xs += __shfl_xor_sync(0xFFFFFFFFu, xs, off);
        if ((tid & 31) == 0) spart[tid >> 5] = xs;
    }
    float bias = sb[0];
    float a0 = bias, a1 = bias, a2 = bias, a3 = bias;
    #pragma unroll
    for (int dh = 0; dh < 5; dh++) {
        const float* row = t + (oh + dh) * 36 + ow4;
        float r0 = row[0], r1 = row[1], r2 = row[2], r3 = row[3];
        float r4 = row[4], r5 = row[5], r6 = row[6], r7 = row[7];
        const float* w = wc + dh * 5;
        float w0 = w[0], w1 = w[1], w2 = w[2], w3v = w[3], w4 = w[4];
        a0 += r0 * w0 + r1 * w1 + r2 * w2 + r3 * w3v + r4 * w4;
        a1 += r1 * w0 + r2 * w1 + r3 * w2 + r4 * w3v + r5 * w4;
        a2 += r2 * w0 + r3 * w1 + r4 * w2 + r5 * w3v + r6 * w4;
        a3 += r3 * w0 + r4 * w1 + r5 * w2 + r6 * w3v + r7 * w4;
    }
    *(float4*)(g_conv + (size_t)bc * HWN + (th + oh) * 256 + tw + ow4) =
        make_float4(a0, a1, a2, a3);
    __syncthreads();
    if (tid == 0) {
        float xs = 0.f;
        #pragma unroll
        for (int k = 0; k < 8; k++) xs += spart[k];
        atomicAdd(&g_xsum[bc], xs);
    }
}

// ---------------- 3) QKV projection (tf32 mma) -> fp16 out + sumsq ----------------
#define QK_ST 68
#define QK_WS (128 * QK_ST)
#define QKV_DYN ((128 * QK_ST + 192 * QK_ST) * 4)   // 87040 bytes

__global__ void __launch_bounds__(256, 2) k_qkv_mma(const float* __restrict__ x,
                                                    const float* __restrict__ wqkv) {
    extern __shared__ float qs[];
    float* As = qs;            // [128 m][68], column-swizzled
    float* Ws = qs + QK_WS;    // [192 n][68]

    int tid = threadIdx.x;
    int wid = tid >> 5, lane = tid & 31;
    int gq = lane >> 2, tq = lane & 3;
    int wm = wid & 1, wn = wid >> 1;
    int mW = wm * 64, nW = wn * 48;

    int bid = blockIdx.x;
    int b = bid >> 9;
    int p0 = (bid & 511) << 7;
    const float* xb = x + (size_t)b * 64 * HWN;

    for (int i = tid; i < 192 * 16; i += 256) {
        int o = i >> 4, c4 = i & 15;
        float4 v = *(const float4*)(wqkv + o * 64 + c4 * 4);
        float* d = Ws + o * QK_ST + c4 * 4;
        d[0] = __uint_as_float(f2tf32(v.x)); d[1] = __uint_as_float(f2tf32(v.y));
        d[2] = __uint_as_float(f2tf32(v.z)); d[3] = __uint_as_float(f2tf32(v.w));
    }
    // A: x[c][p0+j] -> As[j][c ^ swz(j)]  (swizzle kills the 8-way store conflict)
    for (int i = tid; i < 8192; i += 256) {
        int c = i >> 7, j = i & 127;
        int cs = c ^ ((j >> 3) & 3);
        As[j * QK_ST + cs] = __uint_as_float(f2tf32(xb[(size_t)c * HWN + p0 + j]));
    }
    __syncthreads();

    float acc[4][6][4];
    #pragma unroll
    for (int mt = 0; mt < 4; mt++)
        #pragma unroll
        for (int nt = 0; nt < 6; nt++)
            #pragma unroll
            for (int j = 0; j < 4; j++) acc[mt][nt][j] = 0.f;

    #pragma unroll
    for (int ks = 0; ks < 8; ks++) {
        int k0 = ks * 8;
        uint32_t bf[6][2];
        #pragma unroll
        for (int nt = 0; nt < 6; nt++) {
            const float* bp = Ws + (nW + nt * 8 + gq) * QK_ST + k0 + tq;
            bf[nt][0] = __float_as_uint(bp[0]);
            bf[nt][1] = __float_as_uint(bp[4]);
        }
        #pragma unroll
        for (int mt = 0; mt < 4; mt++) {
            int m = mW + mt * 16 + gq;
            int sz0 = (m >> 3) & 3, sz1 = ((m + 8) >> 3) & 3;
            const float* r0p = As + m * QK_ST;
            const float* r1p = As + (m + 8) * QK_ST;
            uint32_t af[4];
            af[0] = __float_as_uint(r0p[(k0 + tq) ^ sz0]);
            af[1] = __float_as_uint(r1p[(k0 + tq) ^ sz1]);
            af[2] = __float_as_uint(r0p[((k0 + tq) ^ sz0) + 4]);
            af[3] = __float_as_uint(r1p[((k0 + tq) ^ sz1) + 4]);
            #pragma unroll
            for (int nt = 0; nt < 6; nt++) MMA8(acc[mt][nt], af, bf[nt]);
        }
    }
    __syncthreads();

    // stage + fp16 store + q/k sum-of-squares, two passes of 96 o-rows
    float* S = qs;
    __half* outb = g_hA + (size_t)b * 192 * HWN + p0;
    #pragma unroll
    for (int pass = 0; pass < 2; pass++) {
        if ((wn >> 1) == pass) {
            int ob = nW - pass * 96;
            #pragma unroll
            for (int mt = 0; mt < 4; mt++) {
                int m = mW + mt * 16 + gq;
                #pragma unroll
                for (int nt = 0; nt < 6; nt++) {
                    int ol = ob + nt * 8 + 2 * tq;
                    S[ol * 132 + m]           = acc[mt][nt][0];
                    S[(ol + 1) * 132 + m]     = acc[mt][nt][1];
                    S[ol * 132 + m + 8]       = acc[mt][nt][2];
                    S[(ol + 1) * 132 + m + 8] = acc[mt][nt][3];
                }
            }
        }
        __syncthreads();
        for (int i = tid; i < 96 * 32; i += 256) {
            int row = i >> 5, q = i & 31;
            float4 v = *(const float4*)(S + row * 132 + q * 4);
            int o = pass * 96 + row;
            uint2 u;
            u.x = h2u(__floats2half2_rn(v.x, v.y));
            u.y = h2u(__floats2half2_rn(v.z, v.w));
            *(uint2*)(outb + (size_t)o * HWN + q * 4) = u;
            if (o < 128) {
                float sq = v.x * v.x + v.y * v.y + v.z * v.z + v.w * v.w;
                #pragma unroll
                for (int off = 16; off; off >>= 1) sq += __shfl_xor_sync(0xFFFFFFFFu, sq, off);
                if ((tid & 31) == 0)
                    atomicAdd(&g_sq[o < 64 ? b * 64 + o : 256 + b * 64 + o - 64], sq);
            }
        }
        __syncthreads();
    }
}

// ---------------- 4) fp16 transpose: g_hA -> g_hT ----------------
__global__ void __launch_bounds__(256) k_tr16() {
    int bid = blockIdx.x;
    int sl = bid >> 6;
    int tile = bid & 63;
    int ty = (tile >> 3) * 32, tx = (tile & 7) * 32;
    const __half* src = g_hA + (size_t)sl * HWN;
    __half* dst = g_hT + (size_t)sl * HWN;
    __shared__ __half t[32 * 34];
    int tid = threadIdx.x;
    int r = tid >> 3, c4 = tid & 7;
    uint2 v = *(const uint2*)(src + (ty + r) * 256 + tx + c4 * 4);
    *(uint32_t*)(&t[r * 34 + c4 * 4])     = v.x;
    *(uint32_t*)(&t[r * 34 + c4 * 4 + 2]) = v.y;
    __syncthreads();
    __half h0 = t[(c4 * 4 + 0) * 34 + r];
    __half h1 = t[(c4 * 4 + 1) * 34 + r];
    __half h2 = t[(c4 * 4 + 2) * 34 + r];
    __half h3 = t[(c4 * 4 + 3) * 34 + r];
    uint2 u;
    u.x = h2u(__halves2half2(h0, h1));
    u.y = h2u(__halves2half2(h2, h3));
    *(uint2*)(dst + (tx + r) * 256 + ty + c4 * 4) = u;
}

// ---------------- 5) fp16 mma dual-axis attention ----------------
// all tile loads are direct coalesced rows (transposes precomputed).
#define HBO 5120                 // A: 128 rows * 40 halves
#define HPO 15360                // + B: 256 * 40
#define ATTN16_DYN ((HPO + 128 * 296) * 2)   // 106496 bytes

__global__ void __launch_bounds__(256, 1) k_attn16(const float* __restrict__ scale) {
    extern __shared__ char dynsm[];
    __half* As = (__half*)dynsm;   // [128][40]
    __half* Bs = As + HBO;         // [256][40]
    __half* Ps = As + HPO;         // [128][296]
    float*  Sf = (float*)dynsm;    // epilogue staging
    __shared__ float s_rows[512];
    __shared__ float s_inv[128];

    int tid = threadIdx.x;
    int wid = tid >> 5, lane = tid & 31;
    int gq = lane >> 2, tq = lane & 3;
    int wm = wid & 1, wn = wid >> 1;
    int mW = wm * 64, nW = wn * 64;

    int bid = blockIdx.x;
    int s = bid & 255, half = (bid >> 8) & 1, dir = bid >> 9;
    int b = s >> 6, ch = s & 63, hd = ch & 7;
    int m0 = half << 7;

    size_t sb = ((size_t)b * 192 + ch) * HWN;
    const __half* Ap  = (dir ? g_hT : g_hA) + sb;
    const __half* B1p = (dir ? g_hT : g_hA) + sb + (size_t)64 * HWN;
    const __half* B2p = (dir ? g_hA : g_hT) + sb + (size_t)128 * HWN;

    float nq = fmaxf(sqrtf(g_sq[s]), 1e-12f);
    float nk = fmaxf(sqrtf(g_sq[256 + s]), 1e-12f);
    float alpha = scale[hd] / (nq * nk);

    float acc[4][8][4];
    #pragma unroll
    for (int mt = 0; mt < 4; mt++)
        #pragma unroll
        for (int nt = 0; nt < 8; nt++)
            #pragma unroll
            for (int j = 0; j < 4; j++) acc[mt][nt][j] = 0.f;

    // ======================= GEMM1: S = A @ B1^T =======================
    for (int cc = 0; cc < 8; cc++) {
        int c0 = cc * 32;
        #pragma unroll
        for (int i = tid; i < 512; i += 256) {
            int r = i >> 2, q = i & 3;
            *(uint4*)(As + r * 40 + q * 8) =
                *(const uint4*)(Ap + (size_t)(m0 + r) * 256 + c0 + q * 8);
        }
        #pragma unroll
        for (int i = tid; i < 1024; i += 256) {
            int r = i >> 2, q = i & 3;
            *(uint4*)(Bs + r * 40 + q * 8) =
                *(const uint4*)(B1p + (size_t)r * 256 + c0 + q * 8);
        }
        __syncthreads();
        #pragma unroll
        for (int ks = 0; ks < 2; ks++) {
            int k0 = ks * 16;
            uint32_t bf[8][2];
            #pragma unroll
            for (int nt = 0; nt < 8; nt++) {
                const __half* bp = Bs + (nW + nt * 8 + gq) * 40 + k0 + 2 * tq;
                bf[nt][0] = *(const uint32_t*)bp;
                bf[nt][1] = *(const uint32_t*)(bp + 8);
            }
            #pragma unroll
            for (int mt = 0; mt < 4; mt++) {
                const __half* ap = As + (mW + mt * 16 + gq) * 40 + k0 + 2 * tq;
                uint32_t af[4];
                af[0] = *(const uint32_t*)ap;
                af[1] = *(const uint32_t*)(ap + 320);
                af[2] = *(const uint32_t*)(ap + 8);
                af[3] = *(const uint32_t*)(ap + 328);
                #pragma unroll
                for (int nt = 0; nt < 8; nt++) MMA16(acc[mt][nt], af, bf[nt]);
            }
        }
        __syncthreads();
    }

    // ======================= softmax =======================
    #pragma unroll
    for (int mt = 0; mt < 4; mt++) {
        int r0 = mW + mt * 16 + gq;
        float rs0 = 0.f, rs1 = 0.f;
        #pragma unroll
        for (int nt = 0; nt < 8; nt++) {
            float e0 = __expf(fminf(acc[mt][nt][0] * alpha, 80.f));
            float e1 = __expf(fminf(acc[mt][nt][1] * alpha, 80.f));
            float e2 = __expf(fminf(acc[mt][nt][2] * alpha, 80.f));
            float e3 = __expf(fminf(acc[mt][nt][3] * alpha, 80.f));
            __half2 h01 = __floats2half2_rn(e0, e1);
            __half2 h23 = __floats2half2_rn(e2, e3);
            float2 f01 = __half22float2(h01);
            float2 f23 = __half22float2(h23);
            rs0 += f01.x + f01.y;
            rs1 += f23.x + f23.y;
            int c = nW + nt * 8 + 2 * tq;
            *(__half2*)(Ps + r0 * 296 + c)       = h01;
            *(__half2*)(Ps + (r0 + 8) * 296 + c) = h23;
        }
        rs0 += __shfl_xor_sync(0xFFFFFFFFu, rs0, 1);
        rs0 += __shfl_xor_sync(0xFFFFFFFFu, rs0, 2);
        rs1 += __shfl_xor_sync(0xFFFFFFFFu, rs1, 1);
        rs1 += __shfl_xor_sync(0xFFFFFFFFu, rs1, 2);
        if (tq == 0) {
            s_rows[wn * 128 + r0]     = rs0;
            s_rows[wn * 128 + r0 + 8] = rs1;
        }
    }
    __syncthreads();
    if (tid < 128)
        s_inv[tid] = 1.0f / (s_rows[tid] + s_rows[128 + tid] + s_rows[256 + tid] + s_rows[384 + tid]);

    #pragma unroll
    for (int mt = 0; mt < 4; mt++)
        #pragma unroll
        for (int nt = 0; nt < 8; nt++)
            #pragma unroll
            for (int j = 0; j < 4; j++) acc[mt][nt][j] = 0.f;
    __syncthreads();

    // ======================= GEMM2: O = P @ B2^T =======================
    for (int cc = 0; cc < 8; cc++) {
        int c0 = cc * 32;
        #pragma unroll
        for (int i = tid; i < 1024; i += 256) {
            int r = i >> 2, q = i & 3;
            *(uint4*)(Bs + r * 40 + q * 8) =
                *(const uint4*)(B2p + (size_t)r * 256 + c0 + q * 8);
        }
        __syncthreads();
        #pragma unroll
        for (int ks = 0; ks < 2; ks++) {
            int k0l = ks * 16;
            uint32_t bf[8][2];
            #pragma unroll
            for (int nt = 0; nt < 8; nt++) {
                const __half* bp = Bs + (nW + nt * 8 + gq) * 40 + k0l + 2 * tq;
                bf[nt][0] = *(const uint32_t*)bp;
                bf[nt][1] = *(const uint32_t*)(bp + 8);
            }
            #pragma unroll
            for (int mt = 0; mt < 4; mt++) {
                const __half* ap = Ps + (mW + mt * 16 + gq) * 296 + c0 + k0l + 2 * tq;
                uint32_t af[4];
                af[0] = *(const uint32_t*)ap;
                af[1] = *(const uint32_t*)(ap + 2368);
                af[2] = *(const uint32_t*)(ap + 8);
                af[3] = *(const uint32_t*)(ap + 2376);
                #pragma unroll
                for (int nt = 0; nt < 8; nt++) MMA16(acc[mt][nt], af, bf[nt]);
            }
        }
        __syncthreads();
    }

    // ======================= epilogue =======================
    if (dir == 0) {
        float* O = g_outh + (size_t)s * HWN;
        #pragma unroll
        for (int pass = 0; pass < 2; pass++) {
            if (wm == pass) {
                #pragma unroll
                for (int mt = 0; mt < 4; mt++) {
                    int rg = mW + mt * 16 + gq;          // global row
                    int rl = mt * 16 + gq;               // local (0..63)
                    float i0 = s_inv[rg], i1 = s_inv[rg + 8];
                    #pragma unroll
                    for (int nt = 0; nt < 8; nt++) {
                        int c = nW + nt * 8 + 2 * tq;
                        *(float2*)(Sf + rl * 260 + c) =
                            make_float2(acc[mt][nt][0] * i0, acc[mt][nt][1] * i0);
                        *(float2*)(Sf + (rl + 8) * 260 + c) =
                            make_float2(acc[mt][nt][2] * i1, acc[mt][nt][3] * i1);
                    }
                }
            }
            __syncthreads();
            for (int i = tid; i < 4096; i += 256) {
                int r = i >> 6, q = i & 63;
                *(float4*)(O + (size_t)(m0 + pass * 64 + r) * 256 + q * 4) =
                    *(const float4*)(Sf + r * 260 + q * 4);
            }
            __syncthreads();
        }
    } else {
        float* O = g_outv + (size_t)s * HWN;
        #pragma unroll
        for (int pass = 0; pass < 2; pass++) {
            if ((wn >> 1) == pass) {
                #pragma unroll
                for (int mt = 0; mt < 4; mt++) {
                    int rg = mW + mt * 16 + gq;
                    float i0 = s_inv[rg], i1 = s_inv[rg + 8];
                    #pragma unroll
                    for (int nt = 0; nt < 8; nt++) {
                        int c = nW + nt * 8 + 2 * tq - pass * 128;
                        Sf[c * 132 + rg]           = acc[mt][nt][0] * i0;
                        Sf[(c + 1) * 132 + rg]     = acc[mt][nt][1] * i0;
                        Sf[c * 132 + rg + 8]       = acc[mt][nt][2] * i1;
                        Sf[(c + 1) * 132 + rg + 8] = acc[mt][nt][3] * i1;
                    }
                }
            }
            __syncthreads();
            for (int i = tid; i < 4096; i += 256) {
                int n = i >> 5, q = i & 31;
                *(float4*)(O + (size_t)(pass * 128 + n) * 256 + m0 + q * 4) =
                    *(const float4*)(Sf + n * 132 + q * 4);
            }
            __syncthreads();
        }
    }
}

// ---------------- 6) gated fusion + projection via tf32 mma ----------------
#define QF_WS (128 * QK_ST)
#define QF_DYN ((128 * QK_ST + 64 * QK_ST) * 4)   // 52224 bytes

__global__ void __launch_bounds__(256, 2) k_fuse_mma(const float* __restrict__ wp,
                                                     const float* __restrict__ bp,
                                                     float* __restrict__ out) {
    extern __shared__ float fs[];
    float* As = fs;            // [128][68] swizzled
    float* Ws = fs + QF_WS;    // [64][68]

    int tid = threadIdx.x;
    int wid = tid >> 5, lane = tid & 31;
    int gq = lane >> 2, tq = lane & 3;
    int wm = wid & 1, wn = wid >> 1;
    int mW = wm * 64, nW = wn * 16;

    int bid = blockIdx.x;
    int b = bid >> 9;
    int p0 = (bid & 511) << 7;
    float cw = g_cw[b], aw = g_aw[b];

    for (int i = tid; i < 64 * 16; i += 256) {
        int o = i >> 4, c4 = i & 15;
        float4 v = *(const float4*)(wp + o * 64 + c4 * 4);
        float* d = Ws + o * QK_ST + c4 * 4;
        d[0] = __uint_as_float(f2tf32(v.x)); d[1] = __uint_as_float(f2tf32(v.y));
        d[2] = __uint_as_float(f2tf32(v.z)); d[3] = __uint_as_float(f2tf32(v.w));
    }
    for (int i = tid; i < 8192; i += 256) {
        int c = i >> 7, j = i & 127;
        size_t off = ((size_t)(b * 64 + c)) * HWN + p0 + j;
        float v = cw * g_conv[off] + aw * (g_outh[off] + g_outv[off]);
        int cs = c ^ ((j >> 3) & 3);
        As[j * QK_ST + cs] = __uint_as_float(f2tf32(v));
    }
    __syncthreads();

    float acc[4][2][4];
    #pragma unroll
    for (int mt = 0; mt < 4; mt++)
        #pragma unroll
        for (int nt = 0; nt < 2; nt++)
            #pragma unroll
            for (int j = 0; j < 4; j++) acc[mt][nt][j] = 0.f;

    #pragma unroll
    for (int ks = 0; ks < 8; ks++) {
        int k0 = ks * 8;
        uint32_t bf[2][2];
        #pragma unroll
        for (int nt = 0; nt < 2; nt++) {
            const float* bpp = Ws + (nW + nt * 8 + gq) * QK_ST + k0 + tq;
            bf[nt][0] = __float_as_uint(bpp[0]);
            bf[nt][1] = __float_as_uint(bpp[4]);
        }
        #pragma unroll
        for (int mt = 0; mt < 4; mt++) {
            int m = mW + mt * 16 + gq;
            int sz0 = (m >> 3) & 3, sz1 = ((m + 8) >> 3) & 3;
            const float* r0p = As + m * QK_ST;
            const float* r1p = As + (m + 8) * QK_ST;
            uint32_t af[4];
            af[0] = __float_as_uint(r0p[(k0 + tq) ^ sz0]);
            af[1] = __float_as_uint(r1p[(k0 + tq) ^ sz1]);
            af[2] = __float_as_uint(r0p[((k0 + tq) ^ sz0) + 4]);
            af[3] = __float_as_uint(r1p[((k0 + tq) ^ sz1) + 4]);
            #pragma unroll
            for (int nt = 0; nt < 2; nt++) MMA8(acc[mt][nt], af, bf[nt]);
        }
    }
    __syncthreads();

    // stage [64 o][132] then coalesced store with bias
    float* S = fs;
    #pragma unroll
    for (int mt = 0; mt < 4; mt++) {
        int m = mW + mt * 16 + gq;
        #pragma unroll
        for (int nt = 0; nt < 2; nt++) {
            int o = nW + nt * 8 + 2 * tq;
            S[o * 132 + m]           = acc[mt][nt][0];
            S[(o + 1) * 132 + m]     = acc[mt][nt][1];
            S[o * 132 + m + 8]       = acc[mt][nt][2];
            S[(o + 1) * 132 + m + 8] = acc[mt][nt][3];
        }
    }
    __syncthreads();
    for (int i = tid; i < 2048; i += 256) {
        int row = i >> 5, q = i & 31;
        float4 v = *(const float4*)(S + row * 132 + q * 4);
        float bb = __ldg(bp + row);
        v.x += bb; v.y += bb; v.z += bb; v.w += bb;
        *(float4*)(out + ((size_t)b * 64 + row) * HWN + p0 + q * 4) = v;
    }
}

// ---------------- launcher ----------------
extern "C" void kernel_launch(void* const* d_in, const int* in_sizes, int n_in,
                              void* d_out, int out_size) {
    const float* x    = (const float*)d_in[0];
    const float* w3   = (const float*)d_in[1];
    const float* b3   = (const float*)d_in[2];
    const float* w5   = (const float*)d_in[3];
    const float* b5   = (const float*)d_in[4];
    const float* wqkv = (const float*)d_in[5];
    const float* scl  = (const float*)d_in[6];
    const float* g1w  = (const float*)d_in[7];
    const float* g1b  = (const float*)d_in[8];
    const float* g2w  = (const float*)d_in[9];
    const float* g2b  = (const float*)d_in[10];
    const float* wp   = (const float*)d_in[11];
    const float* bp   = (const float*)d_in[12];
    float* out = (float*)d_out;

    static bool configured = []() {
        cudaFuncSetAttribute(k_attn16, cudaFuncAttributeMaxDynamicSharedMemorySize, ATTN16_DYN);
        cudaFuncSetAttribute(k_qkv_mma, cudaFuncAttributeMaxDynamicSharedMemorySize, QKV_DYN);
        cudaFuncSetAttribute(k_fuse_mma, cudaFuncAttributeMaxDynamicSharedMemorySize, QF_DYN);
        return true;
    }();
    (void)configured;

    k_zero<<<1, 512>>>();
    k_conv_t<<<16384, 256>>>(x, w3, b3, w5, b5);
    k_qkv_mma<<<2048, 256, QKV_DYN>>>(x, wqkv);
    k_gate<<<1, 32>>>(g1w, g1b, g2w, g2b);
    k_tr16<<<49152, 256>>>();
    k_attn16<<<1024, 256, ATTN16_DYN>>>(scl);
    k_fuse_mma<<<2048, 256, QF_DYN>>>(wp, bp, out);
}

// round 6
// speedup vs baseline: 4.1863x; 1.1629x over previous
#include <cuda_runtime.h>
#include <cuda_fp16.h>
#include <math.h>
#include <stdint.h>

#define BSZ 4
#define DIM 64
#define HWN 65536          // 256*256

// ---------------- device scratch (static, allocation-free) ----------------
__device__ __align__(16) __half g_hA[BSZ * 192 * HWN];   // qkv fp16, [slice][x*256+y]
__device__ __align__(16) __half g_hT[BSZ * 192 * HWN];   // fp16 transposed [y*256+x]
__device__ float g_conv[BSZ * DIM * HWN];
__device__ float g_outh[BSZ * DIM * HWN];
__device__ float g_outv[BSZ * DIM * HWN];
__device__ float g_xsum[BSZ * DIM];
__device__ float g_cw  [BSZ];
__device__ float g_aw  [BSZ];
__device__ float g_sq  [2 * BSZ * DIM];     // [0..255]=sum q^2, [256..511]=sum k^2

// ============================ helpers ============================
__device__ __forceinline__ uint32_t f2tf32(float f) {
    uint32_t u;
    asm("cvt.rna.tf32.f32 %0, %1;" : "=r"(u) : "f"(f));
    return u;
}

#define MMA8(d, a, b) \
    asm volatile("mma.sync.aligned.m16n8k8.row.col.f32.tf32.tf32.f32 " \
        "{%0,%1,%2,%3},{%4,%5,%6,%7},{%8,%9},{%0,%1,%2,%3};" \
        : "+f"((d)[0]), "+f"((d)[1]), "+f"((d)[2]), "+f"((d)[3]) \
        : "r"((a)[0]), "r"((a)[1]), "r"((a)[2]), "r"((a)[3]), \
          "r"((b)[0]), "r"((b)[1]))

#define MMA16(d, a, b) \
    asm volatile("mma.sync.aligned.m16n8k16.row.col.f32.f16.f16.f32 " \
        "{%0,%1,%2,%3},{%4,%5,%6,%7},{%8,%9},{%0,%1,%2,%3};" \
        : "+f"((d)[0]), "+f"((d)[1]), "+f"((d)[2]), "+f"((d)[3]) \
        : "r"((a)[0]), "r"((a)[1]), "r"((a)[2]), "r"((a)[3]), \
          "r"((b)[0]), "r"((b)[1]))

#define CPA16(dst_u32, src_ptr) \
    asm volatile("cp.async.ca.shared.global [%0], [%1], 16;" \
        :: "r"(dst_u32), "l"(src_ptr) : "memory")
#define CP_COMMIT() asm volatile("cp.async.commit_group;" ::: "memory")
#define CP_WAIT(n)  asm volatile("cp.async.wait_group %0;" :: "n"(n) : "memory")

__device__ __forceinline__ uint32_t h2u(__half2 h) {
    return *reinterpret_cast<uint32_t*>(&h);
}

// ---------------- 0) zero accumulators ----------------
__global__ void k_zero() {
    int t = threadIdx.x;
    if (t < 256) g_xsum[t] = 0.f;
    g_sq[t] = 0.f; g_sq[t + 256] = 0.f;
}

// ---------------- 1) gate MLP (parallel: 64 threads) ----------------
__global__ void k_gate(const float* __restrict__ g1w, const float* __restrict__ g1b,
                       const float* __restrict__ g2w, const float* __restrict__ g2b) {
    int tid = threadIdx.x;
    int b = tid >> 4, j = tid & 15;
    __shared__ float sh1[4][16];
    float a = g1b[j];
    #pragma unroll
    for (int c = 0; c < 64; c++)
        a += (g_xsum[b * 64 + c] * (1.0f / HWN)) * g1w[j * 64 + c];
    sh1[b][j] = fmaxf(a, 0.f);
    __syncthreads();
    if (tid < 4) {
        float l0 = g2b[0], l1 = g2b[1];
        #pragma unroll
        for (int k = 0; k < 16; k++) {
            l0 += sh1[tid][k] * g2w[k];
            l1 += sh1[tid][k] * g2w[16 + k];
        }
        float m = fmaxf(l0, l1);
        float e0 = expf(l0 - m), e1 = expf(l1 - m);
        float inv = 1.f / (e0 + e1);
        g_cw[tid] = e0 * inv;
        g_aw[tid] = e1 * inv;
    }
}

// ---------------- 2) tiled fused depthwise conv + channel-mean ----------------
__global__ void __launch_bounds__(256) k_conv_t(const float* __restrict__ x,
                       const float* __restrict__ w3, const float* __restrict__ b3,
                       const float* __restrict__ w5, const float* __restrict__ b5) {
    int bid = blockIdx.x;
    int bc = bid >> 6;
    int tile = bid & 63;
    int th = (tile >> 3) * 32, tw = (tile & 7) * 32;
    int c = bc & 63;
    int tid = threadIdx.x;

    __shared__ float t[36 * 36];
    __shared__ float wc[25];
    __shared__ float sb[1];
    __shared__ float spart[8];
    if (tid < 25) {
        float w = w5[c * 25 + tid];
        int dh = tid / 5 - 2, dw = tid % 5 - 2;
        if (dh >= -1 && dh <= 1 && dw >= -1 && dw <= 1)
            w += w3[c * 9 + (dh + 1) * 3 + (dw + 1)];
        wc[tid] = w;
    }
    if (tid == 25) sb[0] = b3[c] + b5[c];

    const float* xp = x + (size_t)bc * HWN;
    for (int i = tid; i < 1296; i += 256) {
        int r = i / 36, col = i - r * 36;
        int gh = th - 2 + r, gw = tw - 2 + col;
        float v = 0.f;
        if ((unsigned)gh < 256u && (unsigned)gw < 256u) v = xp[gh * 256 + gw];
        t[i] = v;
    }
    __syncthreads();

    int oh = tid >> 3, ow4 = (tid & 7) * 4;
    {
        const float* rp = t + (oh + 2) * 36 + ow4 + 2;
        float xs = rp[0] + rp[1] + rp[2] + rp[3];
        #pragma unroll
        for (int off = 16; off; off >>= 1) xs += __shfl_xor_sync(0xFFFFFFFFu, xs, off);
        if ((tid & 31) == 0) spart[tid >> 5] = xs;
    }
    float bias = sb[0];
    float a0 = bias, a1 = bias, a2 = bias, a3 = bias;
    #pragma unroll
    for (int dh = 0; dh < 5; dh++) {
        const float* row = t + (oh + dh) * 36 + ow4;
        float r0 = row[0], r1 = row[1], r2 = row[2], r3 = row[3];
        float r4 = row[4], r5 = row[5], r6 = row[6], r7 = row[7];
        const float* w = wc + dh * 5;
        float w0 = w[0], w1 = w[1], w2 = w[2], w3v = w[3], w4 = w[4];
        a0 += r0 * w0 + r1 * w1 + r2 * w2 + r3 * w3v + r4 * w4;
        a1 += r1 * w0 + r2 * w1 + r3 * w2 + r4 * w3v + r5 * w4;
        a2 += r2 * w0 + r3 * w1 + r4 * w2 + r5 * w3v + r6 * w4;
        a3 += r3 * w0 + r4 * w1 + r5 * w2 + r6 * w3v + r7 * w4;
    }
    *(float4*)(g_conv + (size_t)bc * HWN + (th + oh) * 256 + tw + ow4) =
        make_float4(a0, a1, a2, a3);
    __syncthreads();
    if (tid == 0) {
        float xs = 0.f;
        #pragma unroll
        for (int k = 0; k < 8; k++) xs += spart[k];
        atomicAdd(&g_xsum[bc], xs);
    }
}

// ---------------- 3) QKV projection (tf32 mma) -> fp16 out + sumsq ----------------
#define QK_ST 68
#define QK_WS (128 * QK_ST)
#define QKV_DYN ((128 * QK_ST + 192 * QK_ST) * 4)   // 87040 bytes

__global__ void __launch_bounds__(256, 2) k_qkv_mma(const float* __restrict__ x,
                                                    const float* __restrict__ wqkv) {
    extern __shared__ float qs[];
    float* As = qs;            // [128 m][68], column-swizzled
    float* Ws = qs + QK_WS;    // [192 n][68]

    int tid = threadIdx.x;
    int wid = tid >> 5, lane = tid & 31;
    int gq = lane >> 2, tq = lane & 3;
    int wm = wid & 1, wn = wid >> 1;
    int mW = wm * 64, nW = wn * 48;

    int bid = blockIdx.x;
    int b = bid >> 9;
    int p0 = (bid & 511) << 7;
    const float* xb = x + (size_t)b * 64 * HWN;

    for (int i = tid; i < 192 * 16; i += 256) {
        int o = i >> 4, c4 = i & 15;
        float4 v = *(const float4*)(wqkv + o * 64 + c4 * 4);
        float* d = Ws + o * QK_ST + c4 * 4;
        d[0] = __uint_as_float(f2tf32(v.x)); d[1] = __uint_as_float(f2tf32(v.y));
        d[2] = __uint_as_float(f2tf32(v.z)); d[3] = __uint_as_float(f2tf32(v.w));
    }
    for (int i = tid; i < 8192; i += 256) {
        int c = i >> 7, j = i & 127;
        int cs = c ^ ((j >> 3) & 3);
        As[j * QK_ST + cs] = __uint_as_float(f2tf32(xb[(size_t)c * HWN + p0 + j]));
    }
    __syncthreads();

    float acc[4][6][4];
    #pragma unroll
    for (int mt = 0; mt < 4; mt++)
        #pragma unroll
        for (int nt = 0; nt < 6; nt++)
            #pragma unroll
            for (int j = 0; j < 4; j++) acc[mt][nt][j] = 0.f;

    #pragma unroll
    for (int ks = 0; ks < 8; ks++) {
        int k0 = ks * 8;
        uint32_t bf[6][2];
        #pragma unroll
        for (int nt = 0; nt < 6; nt++) {
            const float* bp = Ws + (nW + nt * 8 + gq) * QK_ST + k0 + tq;
            bf[nt][0] = __float_as_uint(bp[0]);
            bf[nt][1] = __float_as_uint(bp[4]);
        }
        #pragma unroll
        for (int mt = 0; mt < 4; mt++) {
            int m = mW + mt * 16 + gq;
            int sz0 = (m >> 3) & 3, sz1 = ((m + 8) >> 3) & 3;
            const float* r0p = As + m * QK_ST;
            const float* r1p = As + (m + 8) * QK_ST;
            uint32_t af[4];
            af[0] = __float_as_uint(r0p[(k0 + tq) ^ sz0]);
            af[1] = __float_as_uint(r1p[(k0 + tq) ^ sz1]);
            af[2] = __float_as_uint(r0p[((k0 + tq) ^ sz0) + 4]);
            af[3] = __float_as_uint(r1p[((k0 + tq) ^ sz1) + 4]);
            #pragma unroll
            for (int nt = 0; nt < 6; nt++) MMA8(acc[mt][nt], af, bf[nt]);
        }
    }
    __syncthreads();

    float* S = qs;
    __half* outb = g_hA + (size_t)b * 192 * HWN + p0;
    #pragma unroll
    for (int pass = 0; pass < 2; pass++) {
        if ((wn >> 1) == pass) {
            int ob = nW - pass * 96;
            #pragma unroll
            for (int mt = 0; mt < 4; mt++) {
                int m = mW + mt * 16 + gq;
                #pragma unroll
                for (int nt = 0; nt < 6; nt++) {
                    int ol = ob + nt * 8 + 2 * tq;
                    S[ol * 132 + m]           = acc[mt][nt][0];
                    S[(ol + 1) * 132 + m]     = acc[mt][nt][1];
                    S[ol * 132 + m + 8]       = acc[mt][nt][2];
                    S[(ol + 1) * 132 + m + 8] = acc[mt][nt][3];
                }
            }
        }
        __syncthreads();
        for (int i = tid; i < 96 * 32; i += 256) {
            int row = i >> 5, q = i & 31;
            float4 v = *(const float4*)(S + row * 132 + q * 4);
            int o = pass * 96 + row;
            uint2 u;
            u.x = h2u(__floats2half2_rn(v.x, v.y));
            u.y = h2u(__floats2half2_rn(v.z, v.w));
            *(uint2*)(outb + (size_t)o * HWN + q * 4) = u;
            if (o < 128) {
                float sq = v.x * v.x + v.y * v.y + v.z * v.z + v.w * v.w;
                #pragma unroll
                for (int off = 16; off; off >>= 1) sq += __shfl_xor_sync(0xFFFFFFFFu, sq, off);
                if ((tid & 31) == 0)
                    atomicAdd(&g_sq[o < 64 ? b * 64 + o : 256 + b * 64 + o - 64], sq);
            }
        }
        __syncthreads();
    }
}

// ---------------- 4) fp16 transpose: g_hA -> g_hT ----------------
__global__ void __launch_bounds__(256) k_tr16() {
    int bid = blockIdx.x;
    int sl = bid >> 6;
    int tile = bid & 63;
    int ty = (tile >> 3) * 32, tx = (tile & 7) * 32;
    const __half* src = g_hA + (size_t)sl * HWN;
    __half* dst = g_hT + (size_t)sl * HWN;
    __shared__ __half t[32 * 34];
    int tid = threadIdx.x;
    int r = tid >> 3, c4 = tid & 7;
    uint2 v = *(const uint2*)(src + (ty + r) * 256 + tx + c4 * 4);
    *(uint32_t*)(&t[r * 34 + c4 * 4])     = v.x;
    *(uint32_t*)(&t[r * 34 + c4 * 4 + 2]) = v.y;
    __syncthreads();
    __half h0 = t[(c4 * 4 + 0) * 34 + r];
    __half h1 = t[(c4 * 4 + 1) * 34 + r];
    __half h2 = t[(c4 * 4 + 2) * 34 + r];
    __half h3 = t[(c4 * 4 + 3) * 34 + r];
    uint2 u;
    u.x = h2u(__halves2half2(h0, h1));
    u.y = h2u(__halves2half2(h2, h3));
    *(uint2*)(dst + (tx + r) * 256 + ty + c4 * 4) = u;
}

// ---------------- 5) fp16 mma attention with cp.async double buffering ----------------
// halves layout: As 2x[128][40] @0, Bs 2x[256][40] @10240, Ps [128][296] @30720
#define H_AS(bi) ((bi) * 5120)
#define H_BS(bi) (10240 + (bi) * 10240)
#define H_PS 30720
#define ATTN16_DYN ((30720 + 128 * 296) * 2)   // 137216 bytes

__global__ void __launch_bounds__(256, 1) k_attn16(const float* __restrict__ scale) {
    extern __shared__ char dynsm[];
    __half* Hs = (__half*)dynsm;
    __half* Ps = Hs + H_PS;
    float*  Sf = (float*)dynsm;    // epilogue staging (aliases everything)
    __shared__ float s_rows[512];
    __shared__ float s_inv[128];

    uint32_t smb = (uint32_t)__cvta_generic_to_shared(dynsm);

    int tid = threadIdx.x;
    int wid = tid >> 5, lane = tid & 31;
    int gq = lane >> 2, tq = lane & 3;
    int wm = wid & 1, wn = wid >> 1;
    int mW = wm * 64, nW = wn * 64;

    int bid = blockIdx.x;
    int s = bid & 255, half = (bid >> 8) & 1, dir = bid >> 9;
    int b = s >> 6, ch = s & 63, hd = ch & 7;
    int m0 = half << 7;

    size_t sbase = ((size_t)b * 192 + ch) * HWN;
    const __half* Ap  = (dir ? g_hT : g_hA) + sbase;
    const __half* B1p = (dir ? g_hT : g_hA) + sbase + (size_t)64 * HWN;
    const __half* B2p = (dir ? g_hA : g_hT) + sbase + (size_t)128 * HWN;

    float nq = fmaxf(sqrtf(g_sq[s]), 1e-12f);
    float nk = fmaxf(sqrtf(g_sq[256 + s]), 1e-12f);
    float alpha = scale[hd] / (nq * nk);

    // per-thread copy coordinates
    int ar0 = tid >> 2, aq = tid & 3;          // A: rows tid>>2 and +64, 4 uint4/row
    int br0 = tid >> 2;                        // B: 4 rows per thread (r0, +64, +128, +192)

    float acc[4][8][4];
    #pragma unroll
    for (int mt = 0; mt < 4; mt++)
        #pragma unroll
        for (int nt = 0; nt < 8; nt++)
            #pragma unroll
            for (int j = 0; j < 4; j++) acc[mt][nt][j] = 0.f;

    // ---- prologue: chunk 0 of A and B1 ----
    {
        int c0 = 0;
        #pragma unroll
        for (int rr = 0; rr < 2; rr++) {
            int r = ar0 + rr * 64;
            CPA16(smb + (H_AS(0) + r * 40 + aq * 8) * 2,
                  Ap + (size_t)(m0 + r) * 256 + c0 + aq * 8);
        }
        #pragma unroll
        for (int rr = 0; rr < 4; rr++) {
            int r = br0 + rr * 64;
            CPA16(smb + (H_BS(0) + r * 40 + aq * 8) * 2,
                  B1p + (size_t)r * 256 + c0 + aq * 8);
        }
        CP_COMMIT();
    }

    // ======================= GEMM1 pipeline =======================
    for (int cc = 0; cc < 8; cc++) {
        if (cc < 7) {
            int c0 = (cc + 1) * 32, bi = (cc + 1) & 1;
            #pragma unroll
            for (int rr = 0; rr < 2; rr++) {
                int r = ar0 + rr * 64;
                CPA16(smb + (H_AS(bi) + r * 40 + aq * 8) * 2,
                      Ap + (size_t)(m0 + r) * 256 + c0 + aq * 8);
            }
            #pragma unroll
            for (int rr = 0; rr < 4; rr++) {
                int r = br0 + rr * 64;
                CPA16(smb + (H_BS(bi) + r * 40 + aq * 8) * 2,
                      B1p + (size_t)r * 256 + c0 + aq * 8);
            }
            CP_COMMIT();
            CP_WAIT(1);
        } else {
            CP_WAIT(0);
        }
        __syncthreads();
        const __half* Asb = Hs + H_AS(cc & 1);
        const __half* Bsb = Hs + H_BS(cc & 1);
        #pragma unroll
        for (int ks = 0; ks < 2; ks++) {
            int k0 = ks * 16;
            uint32_t bf[8][2];
            #pragma unroll
            for (int nt = 0; nt < 8; nt++) {
                const __half* bp = Bsb + (nW + nt * 8 + gq) * 40 + k0 + 2 * tq;
                bf[nt][0] = *(const uint32_t*)bp;
                bf[nt][1] = *(const uint32_t*)(bp + 8);
            }
            #pragma unroll
            for (int mt = 0; mt < 4; mt++) {
                const __half* ap = Asb + (mW + mt * 16 + gq) * 40 + k0 + 2 * tq;
                uint32_t af[4];
                af[0] = *(const uint32_t*)ap;
                af[1] = *(const uint32_t*)(ap + 320);
                af[2] = *(const uint32_t*)(ap + 8);
                af[3] = *(const uint32_t*)(ap + 328);
                #pragma unroll
                for (int nt = 0; nt < 8; nt++) MMA16(acc[mt][nt], af, bf[nt]);
            }
        }
        __syncthreads();
    }

    // ---- prologue for GEMM2: B2 chunk 0 flies under the softmax ----
    {
        #pragma unroll
        for (int rr = 0; rr < 4; rr++) {
            int r = br0 + rr * 64;
            CPA16(smb + (H_BS(0) + r * 40 + aq * 8) * 2,
                  B2p + (size_t)r * 256 + aq * 8);
        }
        CP_COMMIT();
    }

    // ======================= softmax =======================
    #pragma unroll
    for (int mt = 0; mt < 4; mt++) {
        int r0 = mW + mt * 16 + gq;
        float rs0 = 0.f, rs1 = 0.f;
        #pragma unroll
        for (int nt = 0; nt < 8; nt++) {
            float e0 = __expf(fminf(acc[mt][nt][0] * alpha, 80.f));
            float e1 = __expf(fminf(acc[mt][nt][1] * alpha, 80.f));
            float e2 = __expf(fminf(acc[mt][nt][2] * alpha, 80.f));
            float e3 = __expf(fminf(acc[mt][nt][3] * alpha, 80.f));
            __half2 h01 = __floats2half2_rn(e0, e1);
            __half2 h23 = __floats2half2_rn(e2, e3);
            float2 f01 = __half22float2(h01);
            float2 f23 = __half22float2(h23);
            rs0 += f01.x + f01.y;
            rs1 += f23.x + f23.y;
            int c = nW + nt * 8 + 2 * tq;
            *(__half2*)(Ps + r0 * 296 + c)       = h01;
            *(__half2*)(Ps + (r0 + 8) * 296 + c) = h23;
        }
        rs0 += __shfl_xor_sync(0xFFFFFFFFu, rs0, 1);
        rs0 += __shfl_xor_sync(0xFFFFFFFFu, rs0, 2);
        rs1 += __shfl_xor_sync(0xFFFFFFFFu, rs1, 1);
        rs1 += __shfl_xor_sync(0xFFFFFFFFu, rs1, 2);
        if (tq == 0) {
            s_rows[wn * 128 + r0]     = rs0;
            s_rows[wn * 128 + r0 + 8] = rs1;
        }
    }
    __syncthreads();
    if (tid < 128)
        s_inv[tid] = 1.0f / (s_rows[tid] + s_rows[128 + tid] + s_rows[256 + tid] + s_rows[384 + tid]);

    #pragma unroll
    for (int mt = 0; mt < 4; mt++)
        #pragma unroll
        for (int nt = 0; nt < 8; nt++)
            #pragma unroll
            for (int j = 0; j < 4; j++) acc[mt][nt][j] = 0.f;

    // ======================= GEMM2 pipeline =======================
    for (int cc = 0; cc < 8; cc++) {
        if (cc < 7) {
            int c0 = (cc + 1) * 32, bi = (cc + 1) & 1;
            #pragma unroll
            for (int rr = 0; rr < 4; rr++) {
                int r = br0 + rr * 64;
                CPA16(smb + (H_BS(bi) + r * 40 + aq * 8) * 2,
                      B2p + (size_t)r * 256 + c0 + aq * 8);
            }
            CP_COMMIT();
            CP_WAIT(1);
        } else {
            CP_WAIT(0);
        }
        __syncthreads();
        const __half* Bsb = Hs + H_BS(cc & 1);
        int c0 = cc * 32;
        #pragma unroll
        for (int ks = 0; ks < 2; ks++) {
            int k0l = ks * 16;
            uint32_t bf[8][2];
            #pragma unroll
            for (int nt = 0; nt < 8; nt++) {
                const __half* bp = Bsb + (nW + nt * 8 + gq) * 40 + k0l + 2 * tq;
                bf[nt][0] = *(const uint32_t*)bp;
                bf[nt][1] = *(const uint32_t*)(bp + 8);
            }
            #pragma unroll
            for (int mt = 0; mt < 4; mt++) {
                const __half* ap = Ps + (mW + mt * 16 + gq) * 296 + c0 + k0l + 2 * tq;
                uint32_t af[4];
                af[0] = *(const uint32_t*)ap;
                af[1] = *(const uint32_t*)(ap + 2368);
                af[2] = *(const uint32_t*)(ap + 8);
                af[3] = *(const uint32_t*)(ap + 2376);
                #pragma unroll
                for (int nt = 0; nt < 8; nt++) MMA16(acc[mt][nt], af, bf[nt]);
            }
        }
        __syncthreads();
    }

    // ======================= epilogue =======================
    if (dir == 0) {
        float* O = g_outh + (size_t)s * HWN;
        #pragma unroll
        for (int pass = 0; pass < 2; pass++) {
            if (wm == pass) {
                #pragma unroll
                for (int mt = 0; mt < 4; mt++) {
                    int rg = mW + mt * 16 + gq;
                    int rl = mt * 16 + gq;
                    float i0 = s_inv[rg], i1 = s_inv[rg + 8];
                    #pragma unroll
                    for (int nt = 0; nt < 8; nt++) {
                        int c = nW + nt * 8 + 2 * tq;
                        *(float2*)(Sf + rl * 260 + c) =
                            make_float2(acc[mt][nt][0] * i0, acc[mt][nt][1] * i0);
                        *(float2*)(Sf + (rl + 8) * 260 + c) =
                            make_float2(acc[mt][nt][2] * i1, acc[mt][nt][3] * i1);
                    }
                }
            }
            __syncthreads();
            for (int i = tid; i < 4096; i += 256) {
                int r = i >> 6, q = i & 63;
                *(float4*)(O + (size_t)(m0 + pass * 64 + r) * 256 + q * 4) =
                    *(const float4*)(Sf + r * 260 + q * 4);
            }
            __syncthreads();
        }
    } else {
        float* O = g_outv + (size_t)s * HWN;
        #pragma unroll
        for (int pass = 0; pass < 2; pass++) {
            if ((wn >> 1) == pass) {
                #pragma unroll
                for (int mt = 0; mt < 4; mt++) {
                    int rg = mW + mt * 16 + gq;
                    float i0 = s_inv[rg], i1 = s_inv[rg + 8];
                    #pragma unroll
                    for (int nt = 0; nt < 8; nt++) {
                        int c = nW + nt * 8 + 2 * tq - pass * 128;
                        Sf[c * 132 + rg]           = acc[mt][nt][0] * i0;
                        Sf[(c + 1) * 132 + rg]     = acc[mt][nt][1] * i0;
                        Sf[c * 132 + rg + 8]       = acc[mt][nt][2] * i1;
                        Sf[(c + 1) * 132 + rg + 8] = acc[mt][nt][3] * i1;
                    }
                }
            }
            __syncthreads();
            for (int i = tid; i < 4096; i += 256) {
                int n = i >> 5, q = i & 31;
                *(float4*)(O + (size_t)(pass * 128 + n) * 256 + m0 + q * 4) =
                    *(const float4*)(Sf + n * 132 + q * 4);
            }
            __syncthreads();
        }
    }
}

// ---------------- 6) gated fusion + projection via tf32 mma ----------------
#define QF_WS (128 * QK_ST)
#define QF_DYN ((128 * QK_ST + 64 * QK_ST) * 4)   // 52224 bytes

__global__ void __launch_bounds__(256, 2) k_fuse_mma(const float* __restrict__ wp,
                                                     const float* __restrict__ bp,
                                                     float* __restrict__ out) {
    extern __shared__ float fs[];
    float* As = fs;            // [128][68] swizzled
    float* Ws = fs + QF_WS;    // [64][68]

    int tid = threadIdx.x;
    int wid = tid >> 5, lane = tid & 31;
    int gq = lane >> 2, tq = lane & 3;
    int wm = wid & 1, wn = wid >> 1;
    int mW = wm * 64, nW = wn * 16;

    int bid = blockIdx.x;
    int b = bid >> 9;
    int p0 = (bid & 511) << 7;
    float cw = g_cw[b], aw = g_aw[b];

    for (int i = tid; i < 64 * 16; i += 256) {
        int o = i >> 4, c4 = i & 15;
        float4 v = *(const float4*)(wp + o * 64 + c4 * 4);
        float* d = Ws + o * QK_ST + c4 * 4;
        d[0] = __uint_as_float(f2tf32(v.x)); d[1] = __uint_as_float(f2tf32(v.y));
        d[2] = __uint_as_float(f2tf32(v.z)); d[3] = __uint_as_float(f2tf32(v.w));
    }
    for (int i = tid; i < 8192; i += 256) {
        int c = i >> 7, j = i & 127;
        size_t off = ((size_t)(b * 64 + c)) * HWN + p0 + j;
        float v = cw * g_conv[off] + aw * (g_outh[off] + g_outv[off]);
        int cs = c ^ ((j >> 3) & 3);
        As[j * QK_ST + cs] = __uint_as_float(f2tf32(v));
    }
    __syncthreads();

    float acc[4][2][4];
    #pragma unroll
    for (int mt = 0; mt < 4; mt++)
        #pragma unroll
        for (int nt = 0; nt < 2; nt++)
            #pragma unroll
            for (int j = 0; j < 4; j++) acc[mt][nt][j] = 0.f;

    #pragma unroll
    for (int ks = 0; ks < 8; ks++) {
        int k0 = ks * 8;
        uint32_t bf[2][2];
        #pragma unroll
        for (int nt = 0; nt < 2; nt++) {
            const float* bpp = Ws + (nW + nt * 8 + gq) * QK_ST + k0 + tq;
            bf[nt][0] = __float_as_uint(bpp[0]);
            bf[nt][1] = __float_as_uint(bpp[4]);
        }
        #pragma unroll
        for (int mt = 0; mt < 4; mt++) {
            int m = mW + mt * 16 + gq;
            int sz0 = (m >> 3) & 3, sz1 = ((m + 8) >> 3) & 3;
            const float* r0p = As + m * QK_ST;
            const float* r1p = As + (m + 8) * QK_ST;
            uint32_t af[4];
            af[0] = __float_as_uint(r0p[(k0 + tq) ^ sz0]);
            af[1] = __float_as_uint(r1p[(k0 + tq) ^ sz1]);
            af[2] = __float_as_uint(r0p[((k0 + tq) ^ sz0) + 4]);
            af[3] = __float_as_uint(r1p[((k0 + tq) ^ sz1) + 4]);
            #pragma unroll
            for (int nt = 0; nt < 2; nt++) MMA8(acc[mt][nt], af, bf[nt]);
        }
    }
    __syncthreads();

    float* S = fs;
    #pragma unroll
    for (int mt = 0; mt < 4; mt++) {
        int m = mW + mt * 16 + gq;
        #pragma unroll
        for (int nt = 0; nt < 2; nt++) {
            int o = nW + nt * 8 + 2 * tq;
            S[o * 132 + m]           = acc[mt][nt][0];
            S[(o + 1) * 132 + m]     = acc[mt][nt][1];
            S[o * 132 + m + 8]       = acc[mt][nt][2];
            S[(o + 1) * 132 + m + 8] = acc[mt][nt][3];
        }
    }
    __syncthreads();
    for (int i = tid; i < 2048; i += 256) {
        int row = i >> 5, q = i & 31;
        float4 v = *(const float4*)(S + row * 132 + q * 4);
        float bb = __ldg(bp + row);
        v.x += bb; v.y += bb; v.z += bb; v.w += bb;
        *(float4*)(out + ((size_t)b * 64 + row) * HWN + p0 + q * 4) = v;
    }
}

// ---------------- launcher ----------------
extern "C" void kernel_launch(void* const* d_in, const int* in_sizes, int n_in,
                              void* d_out, int out_size) {
    const float* x    = (const float*)d_in[0];
    const float* w3   = (const float*)d_in[1];
    const float* b3   = (const float*)d_in[2];
    const float* w5   = (const float*)d_in[3];
    const float* b5   = (const float*)d_in[4];
    const float* wqkv = (const float*)d_in[5];
    const float* scl  = (const float*)d_in[6];
    const float* g1w  = (const float*)d_in[7];
    const float* g1b  = (const float*)d_in[8];
    const float* g2w  = (const float*)d_in[9];
    const float* g2b  = (const float*)d_in[10];
    const float* wp   = (const float*)d_in[11];
    const float* bp   = (const float*)d_in[12];
    float* out = (float*)d_out;

    static bool configured = []() {
        cudaFuncSetAttribute(k_attn16, cudaFuncAttributeMaxDynamicSharedMemorySize, ATTN16_DYN);
        cudaFuncSetAttribute(k_qkv_mma, cudaFuncAttributeMaxDynamicSharedMemorySize, QKV_DYN);
        cudaFuncSetAttribute(k_fuse_mma, cudaFuncAttributeMaxDynamicSharedMemorySize, QF_DYN);
        return true;
    }();
    (void)configured;

    k_zero<<<1, 512>>>();
    k_conv_t<<<16384, 256>>>(x, w3, b3, w5, b5);
    k_qkv_mma<<<2048, 256, QKV_DYN>>>(x, wqkv);
    k_gate<<<1, 64>>>(g1w, g1b, g2w, g2b);
    k_tr16<<<49152, 256>>>();
    k_attn16<<<1024, 256, ATTN16_DYN>>>(scl);
    k_fuse_mma<<<2048, 256, QF_DYN>>>(wp, bp, out);
}